// round 6
// baseline (speedup 1.0000x reference)
#include <cuda_runtime.h>
#include <cstdint>

#define SSCALE 1.6666666666666667f

__device__ __forceinline__ float ssilu(float x) {
    float e = __expf(-x);
    return SSCALE * __fdividef(x, 1.0f + e);
}

// ---- packed f32x2 helpers ----
__device__ __forceinline__ unsigned long long dup2(float x) {
    unsigned long long r;
    asm("mov.b64 %0, {%1, %1};" : "=l"(r) : "f"(x));
    return r;
}
__device__ __forceinline__ unsigned long long pk2(float x, float y) {
    unsigned long long r;
    asm("mov.b64 %0, {%1, %2};" : "=l"(r) : "f"(x), "f"(y));
    return r;
}
__device__ __forceinline__ void up2(float& x, float& y, unsigned long long v) {
    asm("mov.b64 {%0, %1}, %2;" : "=f"(x), "=f"(y) : "l"(v));
}
#define FMA2(d, a, b) asm("fma.rn.f32x2 %0, %1, %2, %0;" : "+l"(d) : "l"(a), "l"(b))
#define ADD2(d, a, b) asm("add.rn.f32x2 %0, %1, %2;" : "=l"(d) : "l"(a), "l"(b))

// ---- bf16 split + mma helpers ----
__device__ __forceinline__ void split2(float v0, float v1, uint32_t& hi, uint32_t& lo) {
    asm("cvt.rn.bf16x2.f32 %0, %1, %2;" : "=r"(hi) : "f"(v1), "f"(v0));
    float h0 = __uint_as_float(hi << 16);
    float h1 = __uint_as_float(hi & 0xFFFF0000u);
    float r0 = v0 - h0, r1 = v1 - h1;
    asm("cvt.rn.bf16x2.f32 %0, %1, %2;" : "=r"(lo) : "f"(r1), "f"(r0));
}
__device__ __forceinline__ void mma_bf16(float* d, uint32_t a0, uint32_t a1,
                                         uint32_t a2, uint32_t a3,
                                         uint32_t b0, uint32_t b1) {
    asm("mma.sync.aligned.m16n8k16.row.col.f32.bf16.bf16.f32 "
        "{%0,%1,%2,%3}, {%4,%5,%6,%7}, {%8,%9}, {%0,%1,%2,%3};"
        : "+f"(d[0]), "+f"(d[1]), "+f"(d[2]), "+f"(d[3])
        : "r"(a0), "r"(a1), "r"(a2), "r"(a3), "r"(b0), "r"(b1));
}
#define LDSM4(d0, d1, d2, d3, a) asm volatile( \
    "ldmatrix.sync.aligned.m8n8.x4.shared.b16 {%0,%1,%2,%3}, [%4];" \
    : "=r"(d0), "=r"(d1), "=r"(d2), "=r"(d3) : "r"(a))
#define LDSM4T(d0, d1, d2, d3, a) asm volatile( \
    "ldmatrix.sync.aligned.m8n8.x4.trans.shared.b16 {%0,%1,%2,%3}, [%4];" \
    : "=r"(d0), "=r"(d1), "=r"(d2), "=r"(d3) : "r"(a))

__device__ __forceinline__ uint32_t smem_u32(const void* p) {
    uint32_t a;
    asm("{ .reg .u64 t; cvta.to.shared.u64 t, %1; cvt.u32.u64 %0, t; }"
        : "=r"(a) : "l"(p));
    return a;
}

#define E_MAX 700000
#define N_MAX 40000
#define T_MAXN 8500000

__device__ __align__(16) float g_xdown[(size_t)E_MAX * 16];
__device__ __align__(16) float g_xe[(size_t)E_MAX * 16];
__device__ __align__(16) float g_h[(size_t)N_MAX * 128];

// CSR scratch
__device__ int g_cnt_e[E_MAX];
__device__ int g_off_e[E_MAX + 1];
__device__ int g_tri[T_MAXN];
__device__ int g_cnt_a[N_MAX];
__device__ int g_off_a[N_MAX + 1];
__device__ int g_eid[E_MAX];
__device__ int g_bsum[512];

// =============== CSR build ===============
__global__ void k_zero_cnt(int E, int N) {
    int i = blockIdx.x * blockDim.x + threadIdx.x;
    int stride = gridDim.x * blockDim.x;
    for (int r = i; r < E; r += stride) g_cnt_e[r] = 0;
    for (int r = i; r < N; r += stride) g_cnt_a[r] = 0;
}

__global__ void k_count(const int* __restrict__ ca, int T,
                        const int* __restrict__ idxt, int E) {
    int i = blockIdx.x * blockDim.x + threadIdx.x;
    int stride = gridDim.x * blockDim.x;
    for (int t = i; t < T; t += stride) atomicAdd(&g_cnt_e[ca[t]], 1);
    for (int e = i; e < E; e += stride) atomicAdd(&g_cnt_a[idxt[e]], 1);
}

#define SCAN_BS 512
#define SCAN_ITEMS 8
#define SCAN_CHUNK 4096

__global__ void k_scan_sums(const int* __restrict__ in, int n, int* bsums) {
    __shared__ int s[SCAN_BS];
    int b = blockIdx.x, tid = threadIdx.x;
    int base = b * SCAN_CHUNK + tid * SCAN_ITEMS;
    int sum = 0;
    #pragma unroll
    for (int i = 0; i < SCAN_ITEMS; i++) {
        int idx = base + i;
        sum += (idx < n) ? in[idx] : 0;
    }
    s[tid] = sum; __syncthreads();
    for (int off = SCAN_BS / 2; off > 0; off >>= 1) {
        if (tid < off) s[tid] += s[tid + off];
        __syncthreads();
    }
    if (tid == 0) bsums[b] = s[0];
}

__global__ void k_scan_top(int* bsums, int nb) {
    __shared__ int s[SCAN_BS];
    int tid = threadIdx.x;
    int v = (tid < nb) ? bsums[tid] : 0;
    s[tid] = v; __syncthreads();
    for (int off = 1; off < SCAN_BS; off <<= 1) {
        int t = (tid >= off) ? s[tid - off] : 0;
        __syncthreads();
        s[tid] += t;
        __syncthreads();
    }
    if (tid < nb) bsums[tid] = s[tid] - v;   // exclusive
}

__global__ void k_scan_out(const int* in, int n, const int* bsums,
                           int* off, int* cur, int total) {
    __shared__ int s[SCAN_BS];
    int b = blockIdx.x, tid = threadIdx.x;
    int base = b * SCAN_CHUNK + tid * SCAN_ITEMS;
    int v[SCAN_ITEMS];
    int sum = 0;
    #pragma unroll
    for (int i = 0; i < SCAN_ITEMS; i++) {
        int idx = base + i;
        v[i] = (idx < n) ? in[idx] : 0;
        sum += v[i];
    }
    s[tid] = sum; __syncthreads();
    for (int o = 1; o < SCAN_BS; o <<= 1) {
        int t = (tid >= o) ? s[tid - o] : 0;
        __syncthreads();
        s[tid] += t;
        __syncthreads();
    }
    int pre = s[tid] - sum + bsums[b];
    #pragma unroll
    for (int i = 0; i < SCAN_ITEMS; i++) {
        int idx = base + i;
        if (idx < n) { off[idx] = pre; cur[idx] = pre; }
        pre += v[i];
    }
    if (b == 0 && tid == 0) off[n] = total;
}

__global__ void k_fill(const int* __restrict__ ca, int T,
                       const int* __restrict__ idxt, int E) {
    int i = blockIdx.x * blockDim.x + threadIdx.x;
    int stride = gridDim.x * blockDim.x;
    for (int t = i; t < T; t += stride) {
        int p = atomicAdd(&g_cnt_e[ca[t]], 1);
        g_tri[p] = t;
    }
    for (int e = i; e < E; e += stride) {
        int p = atomicAdd(&g_cnt_a[idxt[e]], 1);
        g_eid[p] = e;
    }
}

// ---------------- K1: edge dense + down projection (HMMA) -----------------
#define OFF_BH  0
#define OFF_BL  34816
#define OFF_WRH 69632
#define OFF_WRL 73984
#define OFF_WD  78336
#define OFF_AH  86784
#define OFF_AL  104192
#define OFF_RBH 121600
#define OFF_RBL 124672
#define K1_SMEM 127744

__global__ __launch_bounds__(256, 1) void k_edge_down_hmma(
    const float* __restrict__ m, const float* __restrict__ rbf,
    const float* __restrict__ Wba, const float* __restrict__ Wrbf,
    const float* __restrict__ Wdown, int E)
{
    extern __shared__ char smem[];
    uint32_t sb = smem_u32(smem);
    int tid = threadIdx.x;
    int l = tid & 31, w = tid >> 5;

    for (int i = tid; i < 8192; i += 256) {
        int k = i >> 6, n = (i & 63) * 2;
        float v0 = Wba[(size_t)k * 128 + n];
        float v1 = Wba[(size_t)k * 128 + n + 1];
        uint32_t hp, lp;
        split2(v0, v1, hp, lp);
        *(uint32_t*)(smem + OFF_BH + k * 272 + n * 2) = hp;
        *(uint32_t*)(smem + OFF_BL + k * 272 + n * 2) = lp;
    }
    for (int i = tid; i < 1024; i += 256) {
        int k = i >> 6, n = (i & 63) * 2;
        float v0 = Wrbf[(size_t)k * 128 + n];
        float v1 = Wrbf[(size_t)k * 128 + n + 1];
        uint32_t hp, lp;
        split2(v0, v1, hp, lp);
        *(uint32_t*)(smem + OFF_WRH + k * 272 + n * 2) = hp;
        *(uint32_t*)(smem + OFF_WRL + k * 272 + n * 2) = lp;
    }
    float* sWdT = (float*)(smem + OFF_WD);
    for (int i = tid; i < 2048; i += 256) {
        int d = i >> 7, j = i & 127;
        sWdT[d * 132 + j] = Wdown[(size_t)j * 16 + d];
    }

    int rowm = (l < 16) ? l : (l - 16);
    int colo = (l < 16) ? 0 : 8;
    int rb = w & 3, ch = w >> 2;

    uint32_t aH = sb + OFF_AH + (rb * 16 + rowm) * 272 + colo * 2;
    uint32_t aL = aH + (OFF_AL - OFF_AH);
    uint32_t rH = sb + OFF_RBH + (rb * 16 + rowm) * 48 + colo * 2;
    uint32_t rL = rH + (OFF_RBL - OFF_RBH);
    uint32_t bH = sb + OFF_BH + rowm * 272 + (ch * 64 + colo) * 2;
    uint32_t bL = bH + (OFF_BL - OFF_BH);
    uint32_t wrH = sb + OFF_WRH + rowm * 272 + (ch * 64 + colo) * 2;
    uint32_t wrL = wrH + (OFF_WRL - OFF_WRH);

    float* sX = (float*)(smem + OFF_AH);

    int ntiles = (E + 63) >> 6;
    for (int tile = blockIdx.x; tile < ntiles; tile += gridDim.x) {
        int e0 = tile << 6;
        __syncthreads();

        #pragma unroll 4
        for (int it = 0; it < 8; it++) {
            int r = tid + it * 256;
            int e = r >> 5, kq = r & 31;
            float4 v = make_float4(0.f, 0.f, 0.f, 0.f);
            if (e0 + e < E) v = *(const float4*)(m + (size_t)(e0 + e) * 128 + kq * 4);
            uint32_t h01, l01, h23, l23;
            split2(v.x, v.y, h01, l01);
            split2(v.z, v.w, h23, l23);
            unsigned long long hh = ((unsigned long long)h23 << 32) | h01;
            unsigned long long ll = ((unsigned long long)l23 << 32) | l01;
            *(unsigned long long*)(smem + OFF_AH + e * 272 + kq * 8) = hh;
            *(unsigned long long*)(smem + OFF_AL + e * 272 + kq * 8) = ll;
        }
        {
            int e = tid >> 2, kp = tid & 3;
            #pragma unroll
            for (int half = 0; half < 2; half++) {
                int k = (kp + half * 4) * 2;
                float2 v = make_float2(0.f, 0.f);
                if (e0 + e < E) v = *(const float2*)(rbf + (size_t)(e0 + e) * 16 + k);
                uint32_t hp, lp;
                split2(v.x, v.y, hp, lp);
                *(uint32_t*)(smem + OFF_RBH + e * 48 + k * 2) = hp;
                *(uint32_t*)(smem + OFF_RBL + e * 48 + k * 2) = lp;
            }
        }
        __syncthreads();

        float rw[8][4];
        #pragma unroll
        for (int t = 0; t < 8; t++) {
            rw[t][0] = 0.f; rw[t][1] = 0.f; rw[t][2] = 0.f; rw[t][3] = 0.f;
        }
        {
            uint32_t ra0, ra1, ra2, ra3, rl0, rl1, rl2, rl3;
            LDSM4(ra0, ra1, ra2, ra3, rH);
            LDSM4(rl0, rl1, rl2, rl3, rL);
            #pragma unroll
            for (int p = 0; p < 4; p++) {
                uint32_t b0, b1, b2, b3, c0, c1, c2, c3;
                LDSM4T(b0, b1, b2, b3, wrH + p * 32);
                LDSM4T(c0, c1, c2, c3, wrL + p * 32);
                mma_bf16(rw[p * 2], ra0, ra1, ra2, ra3, b0, b1);
                mma_bf16(rw[p * 2], rl0, rl1, rl2, rl3, b0, b1);
                mma_bf16(rw[p * 2], ra0, ra1, ra2, ra3, c0, c1);
                mma_bf16(rw[p * 2 + 1], ra0, ra1, ra2, ra3, b2, b3);
                mma_bf16(rw[p * 2 + 1], rl0, rl1, rl2, rl3, b2, b3);
                mma_bf16(rw[p * 2 + 1], ra0, ra1, ra2, ra3, c2, c3);
            }
        }

        float acc[8][4];
        #pragma unroll
        for (int t = 0; t < 8; t++) {
            acc[t][0] = 0.f; acc[t][1] = 0.f; acc[t][2] = 0.f; acc[t][3] = 0.f;
        }
        #pragma unroll
        for (int ks = 0; ks < 8; ks++) {
            uint32_t ah0, ah1, ah2, ah3, al0, al1, al2, al3;
            LDSM4(ah0, ah1, ah2, ah3, aH + ks * 32);
            LDSM4(al0, al1, al2, al3, aL + ks * 32);
            uint32_t bkb = bH + ks * 16 * 272;
            uint32_t lkb = bL + ks * 16 * 272;
            #pragma unroll
            for (int p = 0; p < 4; p++) {
                uint32_t b0, b1, b2, b3, c0, c1, c2, c3;
                LDSM4T(b0, b1, b2, b3, bkb + p * 32);
                LDSM4T(c0, c1, c2, c3, lkb + p * 32);
                mma_bf16(acc[p * 2], ah0, ah1, ah2, ah3, b0, b1);
                mma_bf16(acc[p * 2], al0, al1, al2, al3, b0, b1);
                mma_bf16(acc[p * 2], ah0, ah1, ah2, ah3, c0, c1);
                mma_bf16(acc[p * 2 + 1], ah0, ah1, ah2, ah3, b2, b3);
                mma_bf16(acc[p * 2 + 1], al0, al1, al2, al3, b2, b3);
                mma_bf16(acc[p * 2 + 1], ah0, ah1, ah2, ah3, c2, c3);
            }
        }

        __syncthreads();

        {
            int r_ = l >> 2, c2 = (l & 3) * 2;
            int row0 = rb * 16 + r_;
            #pragma unroll
            for (int t = 0; t < 8; t++) {
                int col = ch * 64 + t * 8 + c2;
                float x0 = ssilu(acc[t][0]) * rw[t][0];
                float x1 = ssilu(acc[t][1]) * rw[t][1];
                float x2 = ssilu(acc[t][2]) * rw[t][2];
                float x3 = ssilu(acc[t][3]) * rw[t][3];
                *(float2*)&sX[row0 * 132 + col] = make_float2(x0, x1);
                *(float2*)&sX[(row0 + 8) * 132 + col] = make_float2(x2, x3);
            }
        }
        __syncthreads();

        for (int o = tid; o < 1024; o += 256) {
            int e = o >> 4, d = o & 15;
            unsigned long long s0 = 0ull, s1 = 0ull;
            #pragma unroll
            for (int j8 = 0; j8 < 16; j8++) {
                ulonglong2 xA = *(ulonglong2*)&sX[e * 132 + j8 * 8];
                ulonglong2 xB = *(ulonglong2*)&sX[e * 132 + j8 * 8 + 4];
                ulonglong2 wA = *(ulonglong2*)&sWdT[d * 132 + j8 * 8];
                ulonglong2 wB = *(ulonglong2*)&sWdT[d * 132 + j8 * 8 + 4];
                FMA2(s0, xA.x, wA.x); FMA2(s1, xA.y, wA.y);
                FMA2(s0, xB.x, wB.x); FMA2(s1, xB.y, wB.y);
            }
            float a, b, c, dd;
            up2(a, b, s0); up2(c, dd, s1);
            if (e0 + e < E) g_xdown[(size_t)(e0 + e) * 16 + d] = (a + b) + (c + dd);
        }
    }
}

// ---------------- K2: triplet gather via CSR (no atomics) -----------------
__global__ __launch_bounds__(256) void k_triplet2(
    const float* __restrict__ cbf, const int* __restrict__ ba,
    const float* __restrict__ Wcbf, int E)
{
    __shared__ __align__(16) float sW[256];   // [s][d]
    int tid = threadIdx.x;
    sW[tid] = Wcbf[tid];
    __syncthreads();

    int i = blockIdx.x * 256 + tid;
    int stride = gridDim.x * 256;
    for (int e = i; e < E; e += stride) {
        int beg = g_off_e[e], end = g_off_e[e + 1];
        unsigned long long acc[8];
        #pragma unroll
        for (int q = 0; q < 8; q++) acc[q] = 0ull;

        for (int idx = beg; idx < end; idx++) {
            int t = g_tri[idx];
            const float4* cp = (const float4*)(cbf + (size_t)t * 16);
            float4 ca4 = cp[0], cb4 = cp[1], cc4 = cp[2], cd4 = cp[3];
            float cv[16] = {ca4.x, ca4.y, ca4.z, ca4.w, cb4.x, cb4.y, cb4.z, cb4.w,
                            cc4.x, cc4.y, cc4.z, cc4.w, cd4.x, cd4.y, cd4.z, cd4.w};

            unsigned long long o2[8];
            #pragma unroll
            for (int q = 0; q < 8; q++) o2[q] = 0ull;
            #pragma unroll
            for (int s = 0; s < 16; s++) {
                unsigned long long cd = dup2(cv[s]);
                ulonglong2 wA = *(ulonglong2*)&sW[s * 16];
                ulonglong2 wB = *(ulonglong2*)&sW[s * 16 + 4];
                ulonglong2 wC = *(ulonglong2*)&sW[s * 16 + 8];
                ulonglong2 wD = *(ulonglong2*)&sW[s * 16 + 12];
                FMA2(o2[0], cd, wA.x); FMA2(o2[1], cd, wA.y);
                FMA2(o2[2], cd, wB.x); FMA2(o2[3], cd, wB.y);
                FMA2(o2[4], cd, wC.x); FMA2(o2[5], cd, wC.y);
                FMA2(o2[6], cd, wD.x); FMA2(o2[7], cd, wD.y);
            }
            int b = ba[t];
            const ulonglong2* xd = (const ulonglong2*)(g_xdown + (size_t)b * 16);
            ulonglong2 x01 = xd[0], x23 = xd[1], x45 = xd[2], x67 = xd[3];
            FMA2(acc[0], o2[0], x01.x); FMA2(acc[1], o2[1], x01.y);
            FMA2(acc[2], o2[2], x23.x); FMA2(acc[3], o2[3], x23.y);
            FMA2(acc[4], o2[4], x45.x); FMA2(acc[5], o2[5], x45.y);
            FMA2(acc[6], o2[6], x67.x); FMA2(acc[7], o2[7], x67.y);
        }
        float* dst = g_xe + (size_t)e * 16;
        ulonglong2 o;
        o.x = acc[0]; o.y = acc[1]; *(ulonglong2*)(dst) = o;
        o.x = acc[2]; o.y = acc[3]; *(ulonglong2*)(dst + 4) = o;
        o.x = acc[4]; o.y = acc[5]; *(ulonglong2*)(dst + 8) = o;
        o.x = acc[6]; o.y = acc[7]; *(ulonglong2*)(dst + 12) = o;
    }
}

// ---------------- K3: atom gather via CSR (no atomics) --------------------
// one warp per atom; h[a] = sum_e (m[e] + ssilu(xe[e]@Wup)) * (rbf[e]@Wra)
__global__ __launch_bounds__(256) void k_atom_gather(
    const float* __restrict__ m, const float* __restrict__ rbf,
    const float* __restrict__ Wup, const float* __restrict__ Wra, int N)
{
    __shared__ __align__(16) float sWup[2048];   // [d][j]
    __shared__ __align__(16) float sWra[2048];   // [s][j]
    int tid = threadIdx.x;
    for (int i = tid; i < 2048; i += 256) { sWup[i] = Wup[i]; sWra[i] = Wra[i]; }
    __syncthreads();

    int lane = tid & 31, w = tid >> 5;
    int jb = lane * 4;

    for (int a = blockIdx.x * 8 + w; a < N; a += gridDim.x * 8) {
        int beg = g_off_a[a], end = g_off_a[a + 1];
        unsigned long long acc0 = 0ull, acc1 = 0ull;

        for (int idx = beg; idx < end; idx++) {
            int e = g_eid[idx];
            float v = (lane < 16) ? g_xe[(size_t)e * 16 + lane]
                                  : rbf[(size_t)e * 16 + lane - 16];
            unsigned long long u0 = 0ull, u1 = 0ull, r0 = 0ull, r1 = 0ull;
            #pragma unroll
            for (int d = 0; d < 16; d++) {
                float xv = __shfl_sync(0xffffffffu, v, d);
                float rv = __shfl_sync(0xffffffffu, v, 16 + d);
                ulonglong2 wu = *(ulonglong2*)&sWup[d * 128 + jb];
                ulonglong2 wr = *(ulonglong2*)&sWra[d * 128 + jb];
                unsigned long long xd = dup2(xv), rd = dup2(rv);
                FMA2(u0, xd, wu.x); FMA2(u1, xd, wu.y);
                FMA2(r0, rd, wr.x); FMA2(r1, rd, wr.y);
            }
            float4 mm = *(const float4*)(m + (size_t)e * 128 + jb);
            float ua, ub, uc, ud, ra, rb_, rc, rd;
            up2(ua, ub, u0); up2(uc, ud, u1);
            up2(ra, rb_, r0); up2(rc, rd, r1);
            float h0 = (mm.x + ssilu(ua)) * ra;
            float h1 = (mm.y + ssilu(ub)) * rb_;
            float h2 = (mm.z + ssilu(uc)) * rc;
            float h3 = (mm.w + ssilu(ud)) * rd;
            unsigned long long p01 = pk2(h0, h1), p23 = pk2(h2, h3);
            ADD2(acc0, acc0, p01);
            ADD2(acc1, acc1, p23);
        }
        float4 out;
        up2(out.x, out.y, acc0);
        up2(out.z, out.w, acc1);
        *(float4*)(g_h + (size_t)a * 128 + jb) = out;
    }
}

// ---------------- K4: atom output GEMM ----------------
__global__ __launch_bounds__(256, 2) void k_atom_out(
    const float* __restrict__ Watom, float* __restrict__ out, int N)
{
    extern __shared__ float sm_[];
    float* sW = sm_;             // 16384 [k][j]
    float* sH = sm_ + 16384;     // 32*132

    int tid = threadIdx.x;
    for (int i = tid; i < 16384; i += 256) sW[i] = Watom[i];

    int ntiles = (N + 31) >> 5;
    int jt = tid & 31, et = tid >> 5;

    for (int tile = blockIdx.x; tile < ntiles; tile += gridDim.x) {
        int r0 = tile << 5;
        __syncthreads();
        for (int r = tid; r < 1024; r += 256) {
            int e = r >> 5, c = r & 31;
            float4 v = make_float4(0.f, 0.f, 0.f, 0.f);
            if (r0 + e < N) v = ((const float4*)(g_h + (size_t)(r0 + e) * 128))[c];
            *((float4*)&sH[e * 132 + c * 4]) = v;
        }
        __syncthreads();

        float acc[4][4];
        #pragma unroll
        for (int i = 0; i < 4; i++) {
            acc[i][0] = 0.f; acc[i][1] = 0.f; acc[i][2] = 0.f; acc[i][3] = 0.f;
        }
        #pragma unroll 4
        for (int k4 = 0; k4 < 32; k4++) {
            float4 mv[4];
            #pragma unroll
            for (int i = 0; i < 4; i++)
                mv[i] = *((float4*)&sH[(et * 4 + i) * 132 + k4 * 4]);
            #pragma unroll
            for (int kk = 0; kk < 4; kk++) {
                float4 w = *((float4*)&sW[(k4 * 4 + kk) * 128 + jt * 4]);
                #pragma unroll
                for (int i = 0; i < 4; i++) {
                    float mk = (kk == 0) ? mv[i].x : (kk == 1) ? mv[i].y
                             : (kk == 2) ? mv[i].z : mv[i].w;
                    acc[i][0] += mk * w.x;
                    acc[i][1] += mk * w.y;
                    acc[i][2] += mk * w.z;
                    acc[i][3] += mk * w.w;
                }
            }
        }
        #pragma unroll
        for (int i = 0; i < 4; i++) {
            int rrow = r0 + et * 4 + i;
            if (rrow < N) {
                float4 v;
                v.x = ssilu(acc[i][0]);
                v.y = ssilu(acc[i][1]);
                v.z = ssilu(acc[i][2]);
                v.w = ssilu(acc[i][3]);
                *((float4*)(out + (size_t)rrow * 128 + jt * 4)) = v;
            }
        }
        __syncthreads();
    }
}

extern "C" void kernel_launch(void* const* d_in, const int* in_sizes, int n_in,
                              void* d_out, int out_size) {
    const float* m     = (const float*)d_in[0];
    const float* rbf   = (const float*)d_in[1];
    const float* cbf   = (const float*)d_in[2];
    const int*   id3ba = (const int*)d_in[3];
    const int*   id3ca = (const int*)d_in[4];
    const int*   idxt  = (const int*)d_in[5];
    const float* Wba   = (const float*)d_in[6];
    const float* Wrbf  = (const float*)d_in[7];
    const float* Wdown = (const float*)d_in[8];
    const float* Wcbf  = (const float*)d_in[9];
    const float* Wup   = (const float*)d_in[10];
    const float* Wra   = (const float*)d_in[11];
    const float* Watom = (const float*)d_in[12];

    int E = in_sizes[0] / 128;
    int T = in_sizes[2] / 16;
    int N = out_size / 128;

    const int k4_smem = (16384 + 32 * 132) * 4;
    cudaFuncSetAttribute(k_edge_down_hmma,
                         cudaFuncAttributeMaxDynamicSharedMemorySize, K1_SMEM);
    cudaFuncSetAttribute(k_atom_out,
                         cudaFuncAttributeMaxDynamicSharedMemorySize, k4_smem);

    int nbE = (E + SCAN_CHUNK - 1) / SCAN_CHUNK;
    int nbA = (N + SCAN_CHUNK - 1) / SCAN_CHUNK;

    int* p_cnt_e; cudaGetSymbolAddress((void**)&p_cnt_e, g_cnt_e);
    int* p_off_e; cudaGetSymbolAddress((void**)&p_off_e, g_off_e);
    int* p_cnt_a; cudaGetSymbolAddress((void**)&p_cnt_a, g_cnt_a);
    int* p_off_a; cudaGetSymbolAddress((void**)&p_off_a, g_off_a);
    int* p_bsum;  cudaGetSymbolAddress((void**)&p_bsum, g_bsum);

    // CSR build
    k_zero_cnt<<<256, 256>>>(E, N);
    k_count<<<2048, 256>>>(id3ca, T, idxt, E);
    k_scan_sums<<<nbE, SCAN_BS>>>(p_cnt_e, E, p_bsum);
    k_scan_top<<<1, SCAN_BS>>>(p_bsum, nbE);
    k_scan_out<<<nbE, SCAN_BS>>>(p_cnt_e, E, p_bsum, p_off_e, p_cnt_e, T);
    k_scan_sums<<<nbA, SCAN_BS>>>(p_cnt_a, N, p_bsum);
    k_scan_top<<<1, SCAN_BS>>>(p_bsum, nbA);
    k_scan_out<<<nbA, SCAN_BS>>>(p_cnt_a, N, p_bsum, p_off_a, p_cnt_a, E);
    k_fill<<<2048, 256>>>(id3ca, T, idxt, E);

    // main pipeline
    k_edge_down_hmma<<<148, 256, K1_SMEM>>>(m, rbf, Wba, Wrbf, Wdown, E);
    k_triplet2<<<2048, 256>>>(cbf, id3ba, Wcbf, E);
    k_atom_gather<<<2500, 256>>>(m, rbf, Wup, Wra, N);
    k_atom_out<<<(N + 31) / 32, 256, k4_smem>>>(Watom, (float*)d_out, N);
}

// round 7
// speedup vs baseline: 1.6233x; 1.6233x over previous
#include <cuda_runtime.h>
#include <cstdint>

#define SSCALE 1.6666666666666667f

__device__ __forceinline__ float ssilu(float x) {
    float e = __expf(-x);
    return SSCALE * __fdividef(x, 1.0f + e);
}

// ---- packed f32x2 helpers ----
__device__ __forceinline__ unsigned long long dup2(float x) {
    unsigned long long r;
    asm("mov.b64 %0, {%1, %1};" : "=l"(r) : "f"(x));
    return r;
}
__device__ __forceinline__ void up2(float& x, float& y, unsigned long long v) {
    asm("mov.b64 {%0, %1}, %2;" : "=f"(x), "=f"(y) : "l"(v));
}
#define FMA2(d, a, b) asm("fma.rn.f32x2 %0, %1, %2, %0;" : "+l"(d) : "l"(a), "l"(b))
#define MUL2(d, a, b) asm("mul.rn.f32x2 %0, %1, %2;" : "=l"(d) : "l"(a), "l"(b))

// ---- bf16 split + mma helpers ----
__device__ __forceinline__ void split2(float v0, float v1, uint32_t& hi, uint32_t& lo) {
    asm("cvt.rn.bf16x2.f32 %0, %1, %2;" : "=r"(hi) : "f"(v1), "f"(v0));
    float h0 = __uint_as_float(hi << 16);
    float h1 = __uint_as_float(hi & 0xFFFF0000u);
    float r0 = v0 - h0, r1 = v1 - h1;
    asm("cvt.rn.bf16x2.f32 %0, %1, %2;" : "=r"(lo) : "f"(r1), "f"(r0));
}
__device__ __forceinline__ void mma_bf16(float* d, uint32_t a0, uint32_t a1,
                                         uint32_t a2, uint32_t a3,
                                         uint32_t b0, uint32_t b1) {
    asm("mma.sync.aligned.m16n8k16.row.col.f32.bf16.bf16.f32 "
        "{%0,%1,%2,%3}, {%4,%5,%6,%7}, {%8,%9}, {%0,%1,%2,%3};"
        : "+f"(d[0]), "+f"(d[1]), "+f"(d[2]), "+f"(d[3])
        : "r"(a0), "r"(a1), "r"(a2), "r"(a3), "r"(b0), "r"(b1));
}
#define LDSM4(d0, d1, d2, d3, a) asm volatile( \
    "ldmatrix.sync.aligned.m8n8.x4.shared.b16 {%0,%1,%2,%3}, [%4];" \
    : "=r"(d0), "=r"(d1), "=r"(d2), "=r"(d3) : "r"(a))
#define LDSM4T(d0, d1, d2, d3, a) asm volatile( \
    "ldmatrix.sync.aligned.m8n8.x4.trans.shared.b16 {%0,%1,%2,%3}, [%4];" \
    : "=r"(d0), "=r"(d1), "=r"(d2), "=r"(d3) : "r"(a))

__device__ __forceinline__ uint32_t smem_u32(const void* p) {
    uint32_t a;
    asm("{ .reg .u64 t; cvta.to.shared.u64 t, %1; cvt.u32.u64 %0, t; }"
        : "=r"(a) : "l"(p));
    return a;
}

#define E_MAX 700000
#define N_MAX 40000

__device__ __align__(16) float g_xdown[(size_t)E_MAX * 16];
__device__ __align__(16) float g_xe[(size_t)E_MAX * 16];
__device__ __align__(16) float g_h[(size_t)N_MAX * 128];

// ---------------- K0: zero scratch ----------------
__global__ void k_zero(int n_xe4, int n_h4) {
    int i = blockIdx.x * blockDim.x + threadIdx.x;
    int stride = gridDim.x * blockDim.x;
    float4 z = make_float4(0.f, 0.f, 0.f, 0.f);
    for (int r = i; r < n_xe4; r += stride) ((float4*)g_xe)[r] = z;
    for (int r = i; r < n_h4; r += stride) ((float4*)g_h)[r] = z;
}

// ---------------- K1: edge dense + down projection (HMMA) -----------------
#define OFF_BH  0
#define OFF_BL  34816
#define OFF_WRH 69632
#define OFF_WRL 73984
#define OFF_WD  78336
#define OFF_AH  86784
#define OFF_AL  104192
#define OFF_RBH 121600
#define OFF_RBL 124672
#define K1_SMEM 127744

__global__ __launch_bounds__(256, 1) void k_edge_down_hmma(
    const float* __restrict__ m, const float* __restrict__ rbf,
    const float* __restrict__ Wba, const float* __restrict__ Wrbf,
    const float* __restrict__ Wdown, int E)
{
    extern __shared__ char smem[];
    uint32_t sb = smem_u32(smem);
    int tid = threadIdx.x;
    int l = tid & 31, w = tid >> 5;

    for (int i = tid; i < 8192; i += 256) {
        int k = i >> 6, n = (i & 63) * 2;
        float v0 = Wba[(size_t)k * 128 + n];
        float v1 = Wba[(size_t)k * 128 + n + 1];
        uint32_t hp, lp;
        split2(v0, v1, hp, lp);
        *(uint32_t*)(smem + OFF_BH + k * 272 + n * 2) = hp;
        *(uint32_t*)(smem + OFF_BL + k * 272 + n * 2) = lp;
    }
    for (int i = tid; i < 1024; i += 256) {
        int k = i >> 6, n = (i & 63) * 2;
        float v0 = Wrbf[(size_t)k * 128 + n];
        float v1 = Wrbf[(size_t)k * 128 + n + 1];
        uint32_t hp, lp;
        split2(v0, v1, hp, lp);
        *(uint32_t*)(smem + OFF_WRH + k * 272 + n * 2) = hp;
        *(uint32_t*)(smem + OFF_WRL + k * 272 + n * 2) = lp;
    }
    float* sWdT = (float*)(smem + OFF_WD);
    for (int i = tid; i < 2048; i += 256) {
        int d = i >> 7, j = i & 127;
        sWdT[d * 132 + j] = Wdown[(size_t)j * 16 + d];
    }

    int rowm = (l < 16) ? l : (l - 16);
    int colo = (l < 16) ? 0 : 8;
    int rb = w & 3, ch = w >> 2;

    uint32_t aH = sb + OFF_AH + (rb * 16 + rowm) * 272 + colo * 2;
    uint32_t aL = aH + (OFF_AL - OFF_AH);
    uint32_t rH = sb + OFF_RBH + (rb * 16 + rowm) * 48 + colo * 2;
    uint32_t rL = rH + (OFF_RBL - OFF_RBH);
    uint32_t bH = sb + OFF_BH + rowm * 272 + (ch * 64 + colo) * 2;
    uint32_t bL = bH + (OFF_BL - OFF_BH);
    uint32_t wrH = sb + OFF_WRH + rowm * 272 + (ch * 64 + colo) * 2;
    uint32_t wrL = wrH + (OFF_WRL - OFF_WRH);

    float* sX = (float*)(smem + OFF_AH);

    int ntiles = (E + 63) >> 6;
    for (int tile = blockIdx.x; tile < ntiles; tile += gridDim.x) {
        int e0 = tile << 6;
        __syncthreads();

        #pragma unroll 4
        for (int it = 0; it < 8; it++) {
            int r = tid + it * 256;
            int e = r >> 5, kq = r & 31;
            float4 v = make_float4(0.f, 0.f, 0.f, 0.f);
            if (e0 + e < E) v = *(const float4*)(m + (size_t)(e0 + e) * 128 + kq * 4);
            uint32_t h01, l01, h23, l23;
            split2(v.x, v.y, h01, l01);
            split2(v.z, v.w, h23, l23);
            unsigned long long hh = ((unsigned long long)h23 << 32) | h01;
            unsigned long long ll = ((unsigned long long)l23 << 32) | l01;
            *(unsigned long long*)(smem + OFF_AH + e * 272 + kq * 8) = hh;
            *(unsigned long long*)(smem + OFF_AL + e * 272 + kq * 8) = ll;
        }
        {
            int e = tid >> 2, kp = tid & 3;
            #pragma unroll
            for (int half = 0; half < 2; half++) {
                int k = (kp + half * 4) * 2;
                float2 v = make_float2(0.f, 0.f);
                if (e0 + e < E) v = *(const float2*)(rbf + (size_t)(e0 + e) * 16 + k);
                uint32_t hp, lp;
                split2(v.x, v.y, hp, lp);
                *(uint32_t*)(smem + OFF_RBH + e * 48 + k * 2) = hp;
                *(uint32_t*)(smem + OFF_RBL + e * 48 + k * 2) = lp;
            }
        }
        __syncthreads();

        float rw[8][4];
        #pragma unroll
        for (int t = 0; t < 8; t++) {
            rw[t][0] = 0.f; rw[t][1] = 0.f; rw[t][2] = 0.f; rw[t][3] = 0.f;
        }
        {
            uint32_t ra0, ra1, ra2, ra3, rl0, rl1, rl2, rl3;
            LDSM4(ra0, ra1, ra2, ra3, rH);
            LDSM4(rl0, rl1, rl2, rl3, rL);
            #pragma unroll
            for (int p = 0; p < 4; p++) {
                uint32_t b0, b1, b2, b3, c0, c1, c2, c3;
                LDSM4T(b0, b1, b2, b3, wrH + p * 32);
                LDSM4T(c0, c1, c2, c3, wrL + p * 32);
                mma_bf16(rw[p * 2], ra0, ra1, ra2, ra3, b0, b1);
                mma_bf16(rw[p * 2], rl0, rl1, rl2, rl3, b0, b1);
                mma_bf16(rw[p * 2], ra0, ra1, ra2, ra3, c0, c1);
                mma_bf16(rw[p * 2 + 1], ra0, ra1, ra2, ra3, b2, b3);
                mma_bf16(rw[p * 2 + 1], rl0, rl1, rl2, rl3, b2, b3);
                mma_bf16(rw[p * 2 + 1], ra0, ra1, ra2, ra3, c2, c3);
            }
        }

        float acc[8][4];
        #pragma unroll
        for (int t = 0; t < 8; t++) {
            acc[t][0] = 0.f; acc[t][1] = 0.f; acc[t][2] = 0.f; acc[t][3] = 0.f;
        }
        #pragma unroll
        for (int ks = 0; ks < 8; ks++) {
            uint32_t ah0, ah1, ah2, ah3, al0, al1, al2, al3;
            LDSM4(ah0, ah1, ah2, ah3, aH + ks * 32);
            LDSM4(al0, al1, al2, al3, aL + ks * 32);
            uint32_t bkb = bH + ks * 16 * 272;
            uint32_t lkb = bL + ks * 16 * 272;
            #pragma unroll
            for (int p = 0; p < 4; p++) {
                uint32_t b0, b1, b2, b3, c0, c1, c2, c3;
                LDSM4T(b0, b1, b2, b3, bkb + p * 32);
                LDSM4T(c0, c1, c2, c3, lkb + p * 32);
                mma_bf16(acc[p * 2], ah0, ah1, ah2, ah3, b0, b1);
                mma_bf16(acc[p * 2], al0, al1, al2, al3, b0, b1);
                mma_bf16(acc[p * 2], ah0, ah1, ah2, ah3, c0, c1);
                mma_bf16(acc[p * 2 + 1], ah0, ah1, ah2, ah3, b2, b3);
                mma_bf16(acc[p * 2 + 1], al0, al1, al2, al3, b2, b3);
                mma_bf16(acc[p * 2 + 1], ah0, ah1, ah2, ah3, c2, c3);
            }
        }

        __syncthreads();

        {
            int r_ = l >> 2, c2 = (l & 3) * 2;
            int row0 = rb * 16 + r_;
            #pragma unroll
            for (int t = 0; t < 8; t++) {
                int col = ch * 64 + t * 8 + c2;
                float x0 = ssilu(acc[t][0]) * rw[t][0];
                float x1 = ssilu(acc[t][1]) * rw[t][1];
                float x2 = ssilu(acc[t][2]) * rw[t][2];
                float x3 = ssilu(acc[t][3]) * rw[t][3];
                *(float2*)&sX[row0 * 132 + col] = make_float2(x0, x1);
                *(float2*)&sX[(row0 + 8) * 132 + col] = make_float2(x2, x3);
            }
        }
        __syncthreads();

        for (int o = tid; o < 1024; o += 256) {
            int e = o >> 4, d = o & 15;
            unsigned long long s0 = 0ull, s1 = 0ull;
            #pragma unroll
            for (int j8 = 0; j8 < 16; j8++) {
                ulonglong2 xA = *(ulonglong2*)&sX[e * 132 + j8 * 8];
                ulonglong2 xB = *(ulonglong2*)&sX[e * 132 + j8 * 8 + 4];
                ulonglong2 wA = *(ulonglong2*)&sWdT[d * 132 + j8 * 8];
                ulonglong2 wB = *(ulonglong2*)&sWdT[d * 132 + j8 * 8 + 4];
                FMA2(s0, xA.x, wA.x); FMA2(s1, xA.y, wA.y);
                FMA2(s0, xB.x, wB.x); FMA2(s1, xB.y, wB.y);
            }
            float a, b, c, dd;
            up2(a, b, s0); up2(c, dd, s1);
            if (e0 + e < E) g_xdown[(size_t)(e0 + e) * 16 + d] = (a + b) + (c + dd);
        }
    }
}

// ---------------- K2: triplet gather/modulate/scatter (FFMA2) -------------
__global__ __launch_bounds__(256) void k_triplet(
    const float* __restrict__ cbf,
    const int* __restrict__ ba, const int* __restrict__ ca,
    const float* __restrict__ Wcbf, int T)
{
    __shared__ __align__(16) float sW[256];   // [s][d]
    int tid = threadIdx.x;
    sW[tid] = Wcbf[tid];
    __syncthreads();

    int t = blockIdx.x * 256 + tid;
    if (t >= T) return;

    float cv[16];
    {
        const float4* cp = (const float4*)(cbf + (size_t)t * 16);
        float4 a = cp[0], b = cp[1], c = cp[2], d = cp[3];
        cv[0]=a.x; cv[1]=a.y; cv[2]=a.z; cv[3]=a.w;
        cv[4]=b.x; cv[5]=b.y; cv[6]=b.z; cv[7]=b.w;
        cv[8]=c.x; cv[9]=c.y; cv[10]=c.z; cv[11]=c.w;
        cv[12]=d.x; cv[13]=d.y; cv[14]=d.z; cv[15]=d.w;
    }

    unsigned long long o2[8];
    #pragma unroll
    for (int q = 0; q < 8; q++) o2[q] = 0ull;
    #pragma unroll
    for (int s = 0; s < 16; s++) {
        unsigned long long cd = dup2(cv[s]);
        ulonglong2 wA = *(ulonglong2*)&sW[s * 16];
        ulonglong2 wB = *(ulonglong2*)&sW[s * 16 + 4];
        ulonglong2 wC = *(ulonglong2*)&sW[s * 16 + 8];
        ulonglong2 wD = *(ulonglong2*)&sW[s * 16 + 12];
        FMA2(o2[0], cd, wA.x); FMA2(o2[1], cd, wA.y);
        FMA2(o2[2], cd, wB.x); FMA2(o2[3], cd, wB.y);
        FMA2(o2[4], cd, wC.x); FMA2(o2[5], cd, wC.y);
        FMA2(o2[6], cd, wD.x); FMA2(o2[7], cd, wD.y);
    }

    int b = ba[t], a = ca[t];
    const ulonglong2* xd = (const ulonglong2*)(g_xdown + (size_t)b * 16);
    float* dst = g_xe + (size_t)a * 16;
    ulonglong2 x01 = xd[0], x23 = xd[1], x45 = xd[2], x67 = xd[3];
    unsigned long long p0, p1;
    float v0, v1, v2, v3;

    MUL2(p0, o2[0], x01.x); MUL2(p1, o2[1], x01.y);
    up2(v0, v1, p0); up2(v2, v3, p1);
    asm volatile("red.global.add.v4.f32 [%0], {%1,%2,%3,%4};"
                 :: "l"(dst), "f"(v0), "f"(v1), "f"(v2), "f"(v3) : "memory");
    MUL2(p0, o2[2], x23.x); MUL2(p1, o2[3], x23.y);
    up2(v0, v1, p0); up2(v2, v3, p1);
    asm volatile("red.global.add.v4.f32 [%0], {%1,%2,%3,%4};"
                 :: "l"(dst + 4), "f"(v0), "f"(v1), "f"(v2), "f"(v3) : "memory");
    MUL2(p0, o2[4], x45.x); MUL2(p1, o2[5], x45.y);
    up2(v0, v1, p0); up2(v2, v3, p1);
    asm volatile("red.global.add.v4.f32 [%0], {%1,%2,%3,%4};"
                 :: "l"(dst + 8), "f"(v0), "f"(v1), "f"(v2), "f"(v3) : "memory");
    MUL2(p0, o2[6], x67.x); MUL2(p1, o2[7], x67.y);
    up2(v0, v1, p0); up2(v2, v3, p1);
    asm volatile("red.global.add.v4.f32 [%0], {%1,%2,%3,%4};"
                 :: "l"(dst + 12), "f"(v0), "f"(v1), "f"(v2), "f"(v3) : "memory");
}

// ---------------- K3: edge up-projection + atom scatter (HMMA) ------------
// u = xe@Wup, rr = rbf@Wra via mma.sync; h[idxt[e]] += (m + ssilu(u))*rr
#define OFF2_UPH 0
#define OFF2_UPL 4352
#define OFF2_RAH 8704
#define OFF2_RAL 13056
#define OFF2_XEH 17408
#define OFF2_XEL 20480
#define OFF2_RBH 23552
#define OFF2_RBL 26624
#define OFF2_IDX 29696
#define K3_SMEM  29952

__global__ __launch_bounds__(256, 2) void k_edge_up_hmma(
    const float* __restrict__ m, const float* __restrict__ rbf,
    const int* __restrict__ idxt,
    const float* __restrict__ Wup, const float* __restrict__ Wra, int E)
{
    __shared__ __align__(16) char smem[K3_SMEM];
    uint32_t sb = smem_u32(smem);
    int tid = threadIdx.x;
    int l = tid & 31, w = tid >> 5;

    // weights [16 k][128 n], stride 272 B, hi/lo split
    for (int i = tid; i < 1024; i += 256) {
        int k = i >> 6, n = (i & 63) * 2;
        float v0 = Wup[(size_t)k * 128 + n], v1 = Wup[(size_t)k * 128 + n + 1];
        uint32_t hp, lp;
        split2(v0, v1, hp, lp);
        *(uint32_t*)(smem + OFF2_UPH + k * 272 + n * 2) = hp;
        *(uint32_t*)(smem + OFF2_UPL + k * 272 + n * 2) = lp;
        v0 = Wra[(size_t)k * 128 + n]; v1 = Wra[(size_t)k * 128 + n + 1];
        split2(v0, v1, hp, lp);
        *(uint32_t*)(smem + OFF2_RAH + k * 272 + n * 2) = hp;
        *(uint32_t*)(smem + OFF2_RAL + k * 272 + n * 2) = lp;
    }

    int rowm = (l < 16) ? l : (l - 16);
    int colo = (l < 16) ? 0 : 8;
    int rb = w & 3, ch = w >> 2;
    int r_ = l >> 2, cc = (l & 3) * 2;

    uint32_t xH = sb + OFF2_XEH + (rb * 16 + rowm) * 48 + colo * 2;
    uint32_t xL = xH + (OFF2_XEL - OFF2_XEH);
    uint32_t rbH = sb + OFF2_RBH + (rb * 16 + rowm) * 48 + colo * 2;
    uint32_t rbL = rbH + (OFF2_RBL - OFF2_RBH);
    uint32_t bUH = sb + OFF2_UPH + rowm * 272 + (ch * 64 + colo) * 2;
    uint32_t bUL = bUH + (OFF2_UPL - OFF2_UPH);
    uint32_t bRH = sb + OFF2_RAH + rowm * 272 + (ch * 64 + colo) * 2;
    uint32_t bRL = bRH + (OFF2_RAL - OFF2_RAH);
    int* sIdx = (int*)(smem + OFF2_IDX);

    int ntiles = (E + 63) >> 6;
    for (int tile = blockIdx.x; tile < ntiles; tile += gridDim.x) {
        int e0 = tile << 6;
        __syncthreads();

        // convert xe/rbf tiles [64][16] -> hi/lo bf16 (stride 48 B)
        {
            int e = tid >> 2, q = tid & 3;
            float4 vx = make_float4(0.f, 0.f, 0.f, 0.f), vr = vx;
            if (e0 + e < E) {
                vx = *(const float4*)(g_xe + (size_t)(e0 + e) * 16 + q * 4);
                vr = *(const float4*)(rbf + (size_t)(e0 + e) * 16 + q * 4);
            }
            uint32_t h01, l01, h23, l23;
            split2(vx.x, vx.y, h01, l01); split2(vx.z, vx.w, h23, l23);
            *(unsigned long long*)(smem + OFF2_XEH + e * 48 + q * 8) =
                ((unsigned long long)h23 << 32) | h01;
            *(unsigned long long*)(smem + OFF2_XEL + e * 48 + q * 8) =
                ((unsigned long long)l23 << 32) | l01;
            split2(vr.x, vr.y, h01, l01); split2(vr.z, vr.w, h23, l23);
            *(unsigned long long*)(smem + OFF2_RBH + e * 48 + q * 8) =
                ((unsigned long long)h23 << 32) | h01;
            *(unsigned long long*)(smem + OFF2_RBL + e * 48 + q * 8) =
                ((unsigned long long)l23 << 32) | l01;
        }
        if (tid < 64) sIdx[tid] = (e0 + tid < E) ? idxt[e0 + tid] : -1;
        __syncthreads();

        uint32_t xh0, xh1, xh2, xh3, xl0, xl1, xl2, xl3;
        uint32_t rh0, rh1, rh2, rh3, rl0, rl1, rl2, rl3;
        LDSM4(xh0, xh1, xh2, xh3, xH);
        LDSM4(xl0, xl1, xl2, xl3, xL);
        LDSM4(rh0, rh1, rh2, rh3, rbH);
        LDSM4(rl0, rl1, rl2, rl3, rbL);

        #pragma unroll
        for (int p = 0; p < 4; p++) {
            float u[2][4], rr[2][4];
            u[0][0]=u[0][1]=u[0][2]=u[0][3]=0.f;
            u[1][0]=u[1][1]=u[1][2]=u[1][3]=0.f;
            rr[0][0]=rr[0][1]=rr[0][2]=rr[0][3]=0.f;
            rr[1][0]=rr[1][1]=rr[1][2]=rr[1][3]=0.f;
            {
                uint32_t b0, b1, b2, b3, c0, c1, c2, c3;
                LDSM4T(b0, b1, b2, b3, bUH + p * 32);
                LDSM4T(c0, c1, c2, c3, bUL + p * 32);
                mma_bf16(u[0], xh0, xh1, xh2, xh3, b0, b1);
                mma_bf16(u[0], xl0, xl1, xl2, xl3, b0, b1);
                mma_bf16(u[0], xh0, xh1, xh2, xh3, c0, c1);
                mma_bf16(u[1], xh0, xh1, xh2, xh3, b2, b3);
                mma_bf16(u[1], xl0, xl1, xl2, xl3, b2, b3);
                mma_bf16(u[1], xh0, xh1, xh2, xh3, c2, c3);
            }
            {
                uint32_t b0, b1, b2, b3, c0, c1, c2, c3;
                LDSM4T(b0, b1, b2, b3, bRH + p * 32);
                LDSM4T(c0, c1, c2, c3, bRL + p * 32);
                mma_bf16(rr[0], rh0, rh1, rh2, rh3, b0, b1);
                mma_bf16(rr[0], rl0, rl1, rl2, rl3, b0, b1);
                mma_bf16(rr[0], rh0, rh1, rh2, rh3, c0, c1);
                mma_bf16(rr[1], rh0, rh1, rh2, rh3, b2, b3);
                mma_bf16(rr[1], rl0, rl1, rl2, rl3, b2, b3);
                mma_bf16(rr[1], rh0, rh1, rh2, rh3, c2, c3);
            }
            // epilogue for t = 2p, 2p+1
            #pragma unroll
            for (int tt = 0; tt < 2; tt++) {
                int col = ch * 64 + (2 * p + tt) * 8 + cc;
                #pragma unroll
                for (int hh = 0; hh < 2; hh++) {
                    int row = rb * 16 + r_ + 8 * hh;
                    int a = sIdx[row];
                    if (a < 0) continue;
                    float2 mm = *(const float2*)(m + (size_t)(e0 + row) * 128 + col);
                    float h0 = (mm.x + ssilu(u[tt][2 * hh])) * rr[tt][2 * hh];
                    float h1 = (mm.y + ssilu(u[tt][2 * hh + 1])) * rr[tt][2 * hh + 1];
                    asm volatile("red.global.add.v2.f32 [%0], {%1,%2};"
                                 :: "l"(g_h + (size_t)a * 128 + col),
                                    "f"(h0), "f"(h1) : "memory");
                }
            }
        }
    }
}

// ---------------- K4: atom output GEMM ----------------
__global__ __launch_bounds__(256, 2) void k_atom_out(
    const float* __restrict__ Watom, float* __restrict__ out, int N)
{
    extern __shared__ float sm_[];
    float* sW = sm_;             // 16384 [k][j]
    float* sH = sm_ + 16384;     // 32*132

    int tid = threadIdx.x;
    for (int i = tid; i < 16384; i += 256) sW[i] = Watom[i];

    int ntiles = (N + 31) >> 5;
    int jt = tid & 31, et = tid >> 5;

    for (int tile = blockIdx.x; tile < ntiles; tile += gridDim.x) {
        int r0 = tile << 5;
        __syncthreads();
        for (int r = tid; r < 1024; r += 256) {
            int e = r >> 5, c = r & 31;
            float4 v = make_float4(0.f, 0.f, 0.f, 0.f);
            if (r0 + e < N) v = ((const float4*)(g_h + (size_t)(r0 + e) * 128))[c];
            *((float4*)&sH[e * 132 + c * 4]) = v;
        }
        __syncthreads();

        float acc[4][4];
        #pragma unroll
        for (int i = 0; i < 4; i++) {
            acc[i][0] = 0.f; acc[i][1] = 0.f; acc[i][2] = 0.f; acc[i][3] = 0.f;
        }
        #pragma unroll 4
        for (int k4 = 0; k4 < 32; k4++) {
            float4 mv[4];
            #pragma unroll
            for (int i = 0; i < 4; i++)
                mv[i] = *((float4*)&sH[(et * 4 + i) * 132 + k4 * 4]);
            #pragma unroll
            for (int kk = 0; kk < 4; kk++) {
                float4 w = *((float4*)&sW[(k4 * 4 + kk) * 128 + jt * 4]);
                #pragma unroll
                for (int i = 0; i < 4; i++) {
                    float mk = (kk == 0) ? mv[i].x : (kk == 1) ? mv[i].y
                             : (kk == 2) ? mv[i].z : mv[i].w;
                    acc[i][0] += mk * w.x;
                    acc[i][1] += mk * w.y;
                    acc[i][2] += mk * w.z;
                    acc[i][3] += mk * w.w;
                }
            }
        }
        #pragma unroll
        for (int i = 0; i < 4; i++) {
            int rrow = r0 + et * 4 + i;
            if (rrow < N) {
                float4 v;
                v.x = ssilu(acc[i][0]);
                v.y = ssilu(acc[i][1]);
                v.z = ssilu(acc[i][2]);
                v.w = ssilu(acc[i][3]);
                *((float4*)(out + (size_t)rrow * 128 + jt * 4)) = v;
            }
        }
        __syncthreads();
    }
}

extern "C" void kernel_launch(void* const* d_in, const int* in_sizes, int n_in,
                              void* d_out, int out_size) {
    const float* m     = (const float*)d_in[0];
    const float* rbf   = (const float*)d_in[1];
    const float* cbf   = (const float*)d_in[2];
    const int*   id3ba = (const int*)d_in[3];
    const int*   id3ca = (const int*)d_in[4];
    const int*   idxt  = (const int*)d_in[5];
    const float* Wba   = (const float*)d_in[6];
    const float* Wrbf  = (const float*)d_in[7];
    const float* Wdown = (const float*)d_in[8];
    const float* Wcbf  = (const float*)d_in[9];
    const float* Wup   = (const float*)d_in[10];
    const float* Wra   = (const float*)d_in[11];
    const float* Watom = (const float*)d_in[12];

    int E = in_sizes[0] / 128;
    int T = in_sizes[2] / 16;
    int N = out_size / 128;

    const int k4_smem = (16384 + 32 * 132) * 4;
    cudaFuncSetAttribute(k_edge_down_hmma,
                         cudaFuncAttributeMaxDynamicSharedMemorySize, K1_SMEM);
    cudaFuncSetAttribute(k_atom_out,
                         cudaFuncAttributeMaxDynamicSharedMemorySize, k4_smem);

    k_zero<<<512, 256>>>((E * 16) / 4, (N * 128) / 4);
    k_edge_down_hmma<<<148, 256, K1_SMEM>>>(m, rbf, Wba, Wrbf, Wdown, E);
    k_triplet<<<(T + 255) / 256, 256>>>(cbf, id3ba, id3ca, Wcbf, T);
    k_edge_up_hmma<<<1184, 256>>>(m, rbf, idxt, Wup, Wra, E);
    k_atom_out<<<(N + 31) / 32, 256, k4_smem>>>(Watom, (float*)d_out, N);
}

// round 8
// speedup vs baseline: 1.7868x; 1.1007x over previous
#include <cuda_runtime.h>
#include <cstdint>

#define SSCALE 1.6666666666666667f

__device__ __forceinline__ float ssilu(float x) {
    float e = __expf(-x);
    return SSCALE * __fdividef(x, 1.0f + e);
}

// ---- packed f32x2 helpers ----
__device__ __forceinline__ unsigned long long dup2(float x) {
    unsigned long long r;
    asm("mov.b64 %0, {%1, %1};" : "=l"(r) : "f"(x));
    return r;
}
__device__ __forceinline__ void up2(float& x, float& y, unsigned long long v) {
    asm("mov.b64 {%0, %1}, %2;" : "=f"(x), "=f"(y) : "l"(v));
}
#define FMA2(d, a, b) asm("fma.rn.f32x2 %0, %1, %2, %0;" : "+l"(d) : "l"(a), "l"(b))
#define MUL2(d, a, b) asm("mul.rn.f32x2 %0, %1, %2;" : "=l"(d) : "l"(a), "l"(b))

// ---- bf16 split + mma helpers ----
__device__ __forceinline__ void split2(float v0, float v1, uint32_t& hi, uint32_t& lo) {
    asm("cvt.rn.bf16x2.f32 %0, %1, %2;" : "=r"(hi) : "f"(v1), "f"(v0));
    float h0 = __uint_as_float(hi << 16);
    float h1 = __uint_as_float(hi & 0xFFFF0000u);
    float r0 = v0 - h0, r1 = v1 - h1;
    asm("cvt.rn.bf16x2.f32 %0, %1, %2;" : "=r"(lo) : "f"(r1), "f"(r0));
}
__device__ __forceinline__ void mma_bf16(float* d, uint32_t a0, uint32_t a1,
                                         uint32_t a2, uint32_t a3,
                                         uint32_t b0, uint32_t b1) {
    asm("mma.sync.aligned.m16n8k16.row.col.f32.bf16.bf16.f32 "
        "{%0,%1,%2,%3}, {%4,%5,%6,%7}, {%8,%9}, {%0,%1,%2,%3};"
        : "+f"(d[0]), "+f"(d[1]), "+f"(d[2]), "+f"(d[3])
        : "r"(a0), "r"(a1), "r"(a2), "r"(a3), "r"(b0), "r"(b1));
}
#define LDSM4(d0, d1, d2, d3, a) asm volatile( \
    "ldmatrix.sync.aligned.m8n8.x4.shared.b16 {%0,%1,%2,%3}, [%4];" \
    : "=r"(d0), "=r"(d1), "=r"(d2), "=r"(d3) : "r"(a))
#define LDSM4T(d0, d1, d2, d3, a) asm volatile( \
    "ldmatrix.sync.aligned.m8n8.x4.trans.shared.b16 {%0,%1,%2,%3}, [%4];" \
    : "=r"(d0), "=r"(d1), "=r"(d2), "=r"(d3) : "r"(a))

__device__ __forceinline__ uint32_t smem_u32(const void* p) {
    uint32_t a;
    asm("{ .reg .u64 t; cvta.to.shared.u64 t, %1; cvt.u32.u64 %0, t; }"
        : "=r"(a) : "l"(p));
    return a;
}

#define E_MAX 700000
#define N_MAX 40000

__device__ __align__(16) float g_xdown[(size_t)E_MAX * 16];
__device__ __align__(16) float g_xe[(size_t)E_MAX * 16];
__device__ __align__(16) float g_h[(size_t)N_MAX * 128];

// ---------------- K0: zero scratch ----------------
__global__ void k_zero(int n_xe4, int n_h4) {
    int i = blockIdx.x * blockDim.x + threadIdx.x;
    int stride = gridDim.x * blockDim.x;
    float4 z = make_float4(0.f, 0.f, 0.f, 0.f);
    for (int r = i; r < n_xe4; r += stride) ((float4*)g_xe)[r] = z;
    for (int r = i; r < n_h4; r += stride) ((float4*)g_h)[r] = z;
}

// ---------------- K1: edge dense + down projection (all HMMA) -------------
// x = ssilu(m@W_ba)*(rbf@W_rbf); g_xdown = x@W_down  (down-proj also HMMA)
#define OFF_BH  0
#define OFF_BL  34816
#define OFF_WRH 69632
#define OFF_WRL 73984
#define OFF_WDH 78336
#define OFF_WDL 82432
#define OFF_AH  86528
#define OFF_AL  103936
#define OFF_RBH 121344
#define OFF_RBL 124416
#define K1_SMEM 127488

__global__ __launch_bounds__(256, 1) void k_edge_down_hmma(
    const float* __restrict__ m, const float* __restrict__ rbf,
    const float* __restrict__ Wba, const float* __restrict__ Wrbf,
    const float* __restrict__ Wdown, int E)
{
    extern __shared__ char smem[];
    uint32_t sb = smem_u32(smem);
    int tid = threadIdx.x;
    int l = tid & 31, w = tid >> 5;

    // W_ba [128k][128n] hi/lo bf16, stride 272 B
    for (int i = tid; i < 8192; i += 256) {
        int k = i >> 6, n = (i & 63) * 2;
        float v0 = Wba[(size_t)k * 128 + n];
        float v1 = Wba[(size_t)k * 128 + n + 1];
        uint32_t hp, lp;
        split2(v0, v1, hp, lp);
        *(uint32_t*)(smem + OFF_BH + k * 272 + n * 2) = hp;
        *(uint32_t*)(smem + OFF_BL + k * 272 + n * 2) = lp;
    }
    // W_rbf [16k][128n]
    for (int i = tid; i < 1024; i += 256) {
        int k = i >> 6, n = (i & 63) * 2;
        float v0 = Wrbf[(size_t)k * 128 + n];
        float v1 = Wrbf[(size_t)k * 128 + n + 1];
        uint32_t hp, lp;
        split2(v0, v1, hp, lp);
        *(uint32_t*)(smem + OFF_WRH + k * 272 + n * 2) = hp;
        *(uint32_t*)(smem + OFF_WRL + k * 272 + n * 2) = lp;
    }
    // W_down [128k][16n] hi/lo bf16, stride 32 B
    for (int i = tid; i < 1024; i += 256) {
        int k = i >> 3, n = (i & 7) * 2;
        float v0 = Wdown[(size_t)k * 16 + n];
        float v1 = Wdown[(size_t)k * 16 + n + 1];
        uint32_t hp, lp;
        split2(v0, v1, hp, lp);
        *(uint32_t*)(smem + OFF_WDH + k * 32 + n * 2) = hp;
        *(uint32_t*)(smem + OFF_WDL + k * 32 + n * 2) = lp;
    }

    int rowm = (l < 16) ? l : (l - 16);
    int colo = (l < 16) ? 0 : 8;
    int rb = w & 3, ch = w >> 2;
    int r_ = l >> 2, cc2 = (l & 3) * 2;

    uint32_t aH = sb + OFF_AH + (rb * 16 + rowm) * 272 + colo * 2;
    uint32_t aL = aH + (OFF_AL - OFF_AH);
    uint32_t rH = sb + OFF_RBH + (rb * 16 + rowm) * 48 + colo * 2;
    uint32_t rL = rH + (OFF_RBL - OFF_RBH);
    uint32_t bH = sb + OFF_BH + rowm * 272 + (ch * 64 + colo) * 2;
    uint32_t bL = bH + (OFF_BL - OFF_BH);
    uint32_t wrH = sb + OFF_WRH + rowm * 272 + (ch * 64 + colo) * 2;
    uint32_t wrL = wrH + (OFF_WRL - OFF_WRH);
    uint32_t wdH = sb + OFF_WDH + rowm * 32 + colo * 2;
    uint32_t wdL = wdH + (OFF_WDL - OFF_WDH);

    char* sXH = smem + OFF_AH;   // X hi aliases A hi (same layout)
    char* sXL = smem + OFF_AL;

    int ntiles = (E + 63) >> 6;
    for (int tile = blockIdx.x; tile < ntiles; tile += gridDim.x) {
        int e0 = tile << 6;
        __syncthreads();   // prev tile fully consumed / weights ready

        // convert m tile [64][128] -> A hi/lo
        #pragma unroll 4
        for (int it = 0; it < 8; it++) {
            int r = tid + it * 256;
            int e = r >> 5, kq = r & 31;
            float4 v = make_float4(0.f, 0.f, 0.f, 0.f);
            if (e0 + e < E) v = *(const float4*)(m + (size_t)(e0 + e) * 128 + kq * 4);
            uint32_t h01, l01, h23, l23;
            split2(v.x, v.y, h01, l01);
            split2(v.z, v.w, h23, l23);
            *(unsigned long long*)(smem + OFF_AH + e * 272 + kq * 8) =
                ((unsigned long long)h23 << 32) | h01;
            *(unsigned long long*)(smem + OFF_AL + e * 272 + kq * 8) =
                ((unsigned long long)l23 << 32) | l01;
        }
        // convert rbf tile [64][16] (stride 48 B)
        {
            int e = tid >> 2, kp = tid & 3;
            #pragma unroll
            for (int half = 0; half < 2; half++) {
                int k = (kp + half * 4) * 2;
                float2 v = make_float2(0.f, 0.f);
                if (e0 + e < E) v = *(const float2*)(rbf + (size_t)(e0 + e) * 16 + k);
                uint32_t hp, lp;
                split2(v.x, v.y, hp, lp);
                *(uint32_t*)(smem + OFF_RBH + e * 48 + k * 2) = hp;
                *(uint32_t*)(smem + OFF_RBL + e * 48 + k * 2) = lp;
            }
        }
        __syncthreads();

        // rw = rbf @ W_rbf (3-pass)
        float rw[8][4];
        #pragma unroll
        for (int t = 0; t < 8; t++) {
            rw[t][0] = 0.f; rw[t][1] = 0.f; rw[t][2] = 0.f; rw[t][3] = 0.f;
        }
        {
            uint32_t ra0, ra1, ra2, ra3, rl0, rl1, rl2, rl3;
            LDSM4(ra0, ra1, ra2, ra3, rH);
            LDSM4(rl0, rl1, rl2, rl3, rL);
            #pragma unroll
            for (int p = 0; p < 4; p++) {
                uint32_t b0, b1, b2, b3, c0, c1, c2, c3;
                LDSM4T(b0, b1, b2, b3, wrH + p * 32);
                LDSM4T(c0, c1, c2, c3, wrL + p * 32);
                mma_bf16(rw[p * 2], ra0, ra1, ra2, ra3, b0, b1);
                mma_bf16(rw[p * 2], rl0, rl1, rl2, rl3, b0, b1);
                mma_bf16(rw[p * 2], ra0, ra1, ra2, ra3, c0, c1);
                mma_bf16(rw[p * 2 + 1], ra0, ra1, ra2, ra3, b2, b3);
                mma_bf16(rw[p * 2 + 1], rl0, rl1, rl2, rl3, b2, b3);
                mma_bf16(rw[p * 2 + 1], ra0, ra1, ra2, ra3, c2, c3);
            }
        }

        // main GEMM m @ W_ba (3-pass)
        float acc[8][4];
        #pragma unroll
        for (int t = 0; t < 8; t++) {
            acc[t][0] = 0.f; acc[t][1] = 0.f; acc[t][2] = 0.f; acc[t][3] = 0.f;
        }
        #pragma unroll
        for (int ks = 0; ks < 8; ks++) {
            uint32_t ah0, ah1, ah2, ah3, al0, al1, al2, al3;
            LDSM4(ah0, ah1, ah2, ah3, aH + ks * 32);
            LDSM4(al0, al1, al2, al3, aL + ks * 32);
            uint32_t bkb = bH + ks * 16 * 272;
            uint32_t lkb = bL + ks * 16 * 272;
            #pragma unroll
            for (int p = 0; p < 4; p++) {
                uint32_t b0, b1, b2, b3, c0, c1, c2, c3;
                LDSM4T(b0, b1, b2, b3, bkb + p * 32);
                LDSM4T(c0, c1, c2, c3, lkb + p * 32);
                mma_bf16(acc[p * 2], ah0, ah1, ah2, ah3, b0, b1);
                mma_bf16(acc[p * 2], al0, al1, al2, al3, b0, b1);
                mma_bf16(acc[p * 2], ah0, ah1, ah2, ah3, c0, c1);
                mma_bf16(acc[p * 2 + 1], ah0, ah1, ah2, ah3, b2, b3);
                mma_bf16(acc[p * 2 + 1], al0, al1, al2, al3, b2, b3);
                mma_bf16(acc[p * 2 + 1], ah0, ah1, ah2, ah3, c2, c3);
            }
        }

        __syncthreads();   // all A reads done; region becomes X hi/lo

        // x = ssilu(acc)*rw -> X hi/lo (A layout, in-register split)
        {
            int row0 = rb * 16 + r_;
            #pragma unroll
            for (int t = 0; t < 8; t++) {
                int colb = (ch * 64 + t * 8 + cc2) * 2;
                float x0 = ssilu(acc[t][0]) * rw[t][0];
                float x1 = ssilu(acc[t][1]) * rw[t][1];
                float x2 = ssilu(acc[t][2]) * rw[t][2];
                float x3 = ssilu(acc[t][3]) * rw[t][3];
                uint32_t hp, lp;
                split2(x0, x1, hp, lp);
                *(uint32_t*)(sXH + row0 * 272 + colb) = hp;
                *(uint32_t*)(sXL + row0 * 272 + colb) = lp;
                split2(x2, x3, hp, lp);
                *(uint32_t*)(sXH + (row0 + 8) * 272 + colb) = hp;
                *(uint32_t*)(sXL + (row0 + 8) * 272 + colb) = lp;
            }
        }
        __syncthreads();

        // down projection via HMMA: X[64x128] @ W_down[128x16] (warps 0-3)
        if (w < 4) {
            float d0[4] = {0.f, 0.f, 0.f, 0.f}, d1[4] = {0.f, 0.f, 0.f, 0.f};
            #pragma unroll
            for (int ks = 0; ks < 8; ks++) {
                uint32_t xh0, xh1, xh2, xh3, xl0, xl1, xl2, xl3;
                LDSM4(xh0, xh1, xh2, xh3, aH + ks * 32);
                LDSM4(xl0, xl1, xl2, xl3, aL + ks * 32);
                uint32_t b0, b1, b2, b3, c0, c1, c2, c3;
                LDSM4T(b0, b1, b2, b3, wdH + ks * 512);
                LDSM4T(c0, c1, c2, c3, wdL + ks * 512);
                mma_bf16(d0, xh0, xh1, xh2, xh3, b0, b1);
                mma_bf16(d0, xl0, xl1, xl2, xl3, b0, b1);
                mma_bf16(d0, xh0, xh1, xh2, xh3, c0, c1);
                mma_bf16(d1, xh0, xh1, xh2, xh3, b2, b3);
                mma_bf16(d1, xl0, xl1, xl2, xl3, b2, b3);
                mma_bf16(d1, xh0, xh1, xh2, xh3, c2, c3);
            }
            int e_row = e0 + rb * 16 + r_;
            if (e_row < E) {
                *(float2*)(g_xdown + (size_t)e_row * 16 + cc2) = make_float2(d0[0], d0[1]);
                *(float2*)(g_xdown + (size_t)e_row * 16 + 8 + cc2) = make_float2(d1[0], d1[1]);
            }
            if (e_row + 8 < E) {
                *(float2*)(g_xdown + (size_t)(e_row + 8) * 16 + cc2) = make_float2(d0[2], d0[3]);
                *(float2*)(g_xdown + (size_t)(e_row + 8) * 16 + 8 + cc2) = make_float2(d1[2], d1[3]);
            }
        }
    }
}

// ---------------- K2: triplet gather/modulate/scatter (FFMA2) -------------
__global__ __launch_bounds__(256) void k_triplet(
    const float* __restrict__ cbf,
    const int* __restrict__ ba, const int* __restrict__ ca,
    const float* __restrict__ Wcbf, int T)
{
    __shared__ __align__(16) float sW[256];   // [s][d]
    int tid = threadIdx.x;
    sW[tid] = Wcbf[tid];
    __syncthreads();

    int t = blockIdx.x * 256 + tid;
    if (t >= T) return;

    float cv[16];
    {
        const float4* cp = (const float4*)(cbf + (size_t)t * 16);
        float4 a = cp[0], b = cp[1], c = cp[2], d = cp[3];
        cv[0]=a.x; cv[1]=a.y; cv[2]=a.z; cv[3]=a.w;
        cv[4]=b.x; cv[5]=b.y; cv[6]=b.z; cv[7]=b.w;
        cv[8]=c.x; cv[9]=c.y; cv[10]=c.z; cv[11]=c.w;
        cv[12]=d.x; cv[13]=d.y; cv[14]=d.z; cv[15]=d.w;
    }

    unsigned long long o2[8];
    #pragma unroll
    for (int q = 0; q < 8; q++) o2[q] = 0ull;
    #pragma unroll
    for (int s = 0; s < 16; s++) {
        unsigned long long cd = dup2(cv[s]);
        ulonglong2 wA = *(ulonglong2*)&sW[s * 16];
        ulonglong2 wB = *(ulonglong2*)&sW[s * 16 + 4];
        ulonglong2 wC = *(ulonglong2*)&sW[s * 16 + 8];
        ulonglong2 wD = *(ulonglong2*)&sW[s * 16 + 12];
        FMA2(o2[0], cd, wA.x); FMA2(o2[1], cd, wA.y);
        FMA2(o2[2], cd, wB.x); FMA2(o2[3], cd, wB.y);
        FMA2(o2[4], cd, wC.x); FMA2(o2[5], cd, wC.y);
        FMA2(o2[6], cd, wD.x); FMA2(o2[7], cd, wD.y);
    }

    int b = ba[t], a = ca[t];
    const ulonglong2* xd = (const ulonglong2*)(g_xdown + (size_t)b * 16);
    float* dst = g_xe + (size_t)a * 16;
    ulonglong2 x01 = xd[0], x23 = xd[1], x45 = xd[2], x67 = xd[3];
    unsigned long long p0, p1;
    float v0, v1, v2, v3;

    MUL2(p0, o2[0], x01.x); MUL2(p1, o2[1], x01.y);
    up2(v0, v1, p0); up2(v2, v3, p1);
    asm volatile("red.global.add.v4.f32 [%0], {%1,%2,%3,%4};"
                 :: "l"(dst), "f"(v0), "f"(v1), "f"(v2), "f"(v3) : "memory");
    MUL2(p0, o2[2], x23.x); MUL2(p1, o2[3], x23.y);
    up2(v0, v1, p0); up2(v2, v3, p1);
    asm volatile("red.global.add.v4.f32 [%0], {%1,%2,%3,%4};"
                 :: "l"(dst + 4), "f"(v0), "f"(v1), "f"(v2), "f"(v3) : "memory");
    MUL2(p0, o2[4], x45.x); MUL2(p1, o2[5], x45.y);
    up2(v0, v1, p0); up2(v2, v3, p1);
    asm volatile("red.global.add.v4.f32 [%0], {%1,%2,%3,%4};"
                 :: "l"(dst + 8), "f"(v0), "f"(v1), "f"(v2), "f"(v3) : "memory");
    MUL2(p0, o2[6], x67.x); MUL2(p1, o2[7], x67.y);
    up2(v0, v1, p0); up2(v2, v3, p1);
    asm volatile("red.global.add.v4.f32 [%0], {%1,%2,%3,%4};"
                 :: "l"(dst + 12), "f"(v0), "f"(v1), "f"(v2), "f"(v3) : "memory");
}

// ---------------- K3: edge up-projection + atom scatter (HMMA) ------------
#define OFF2_UPH 0
#define OFF2_UPL 4352
#define OFF2_RAH 8704
#define OFF2_RAL 13056
#define OFF2_XEH 17408
#define OFF2_XEL 20480
#define OFF2_RBH 23552
#define OFF2_RBL 26624
#define OFF2_IDX 29696
#define K3_SMEM  29952

__global__ __launch_bounds__(256, 2) void k_edge_up_hmma(
    const float* __restrict__ m, const float* __restrict__ rbf,
    const int* __restrict__ idxt,
    const float* __restrict__ Wup, const float* __restrict__ Wra, int E)
{
    __shared__ __align__(16) char smem[K3_SMEM];
    uint32_t sb = smem_u32(smem);
    int tid = threadIdx.x;
    int l = tid & 31, w = tid >> 5;

    for (int i = tid; i < 1024; i += 256) {
        int k = i >> 6, n = (i & 63) * 2;
        float v0 = Wup[(size_t)k * 128 + n], v1 = Wup[(size_t)k * 128 + n + 1];
        uint32_t hp, lp;
        split2(v0, v1, hp, lp);
        *(uint32_t*)(smem + OFF2_UPH + k * 272 + n * 2) = hp;
        *(uint32_t*)(smem + OFF2_UPL + k * 272 + n * 2) = lp;
        v0 = Wra[(size_t)k * 128 + n]; v1 = Wra[(size_t)k * 128 + n + 1];
        split2(v0, v1, hp, lp);
        *(uint32_t*)(smem + OFF2_RAH + k * 272 + n * 2) = hp;
        *(uint32_t*)(smem + OFF2_RAL + k * 272 + n * 2) = lp;
    }

    int rowm = (l < 16) ? l : (l - 16);
    int colo = (l < 16) ? 0 : 8;
    int rb = w & 3, ch = w >> 2;
    int r_ = l >> 2, cc = (l & 3) * 2;

    uint32_t xH = sb + OFF2_XEH + (rb * 16 + rowm) * 48 + colo * 2;
    uint32_t xL = xH + (OFF2_XEL - OFF2_XEH);
    uint32_t rbH = sb + OFF2_RBH + (rb * 16 + rowm) * 48 + colo * 2;
    uint32_t rbL = rbH + (OFF2_RBL - OFF2_RBH);
    uint32_t bUH = sb + OFF2_UPH + rowm * 272 + (ch * 64 + colo) * 2;
    uint32_t bUL = bUH + (OFF2_UPL - OFF2_UPH);
    uint32_t bRH = sb + OFF2_RAH + rowm * 272 + (ch * 64 + colo) * 2;
    uint32_t bRL = bRH + (OFF2_RAL - OFF2_RAH);
    int* sIdx = (int*)(smem + OFF2_IDX);

    int ntiles = (E + 63) >> 6;
    for (int tile = blockIdx.x; tile < ntiles; tile += gridDim.x) {
        int e0 = tile << 6;
        __syncthreads();

        {
            int e = tid >> 2, q = tid & 3;
            float4 vx = make_float4(0.f, 0.f, 0.f, 0.f), vr = vx;
            if (e0 + e < E) {
                vx = *(const float4*)(g_xe + (size_t)(e0 + e) * 16 + q * 4);
                vr = *(const float4*)(rbf + (size_t)(e0 + e) * 16 + q * 4);
            }
            uint32_t h01, l01, h23, l23;
            split2(vx.x, vx.y, h01, l01); split2(vx.z, vx.w, h23, l23);
            *(unsigned long long*)(smem + OFF2_XEH + e * 48 + q * 8) =
                ((unsigned long long)h23 << 32) | h01;
            *(unsigned long long*)(smem + OFF2_XEL + e * 48 + q * 8) =
                ((unsigned long long)l23 << 32) | l01;
            split2(vr.x, vr.y, h01, l01); split2(vr.z, vr.w, h23, l23);
            *(unsigned long long*)(smem + OFF2_RBH + e * 48 + q * 8) =
                ((unsigned long long)h23 << 32) | h01;
            *(unsigned long long*)(smem + OFF2_RBL + e * 48 + q * 8) =
                ((unsigned long long)l23 << 32) | l01;
        }
        if (tid < 64) sIdx[tid] = (e0 + tid < E) ? idxt[e0 + tid] : -1;
        __syncthreads();

        uint32_t xh0, xh1, xh2, xh3, xl0, xl1, xl2, xl3;
        uint32_t rh0, rh1, rh2, rh3, rl0, rl1, rl2, rl3;
        LDSM4(xh0, xh1, xh2, xh3, xH);
        LDSM4(xl0, xl1, xl2, xl3, xL);
        LDSM4(rh0, rh1, rh2, rh3, rbH);
        LDSM4(rl0, rl1, rl2, rl3, rbL);

        #pragma unroll
        for (int p = 0; p < 4; p++) {
            float u[2][4], rr[2][4];
            u[0][0]=u[0][1]=u[0][2]=u[0][3]=0.f;
            u[1][0]=u[1][1]=u[1][2]=u[1][3]=0.f;
            rr[0][0]=rr[0][1]=rr[0][2]=rr[0][3]=0.f;
            rr[1][0]=rr[1][1]=rr[1][2]=rr[1][3]=0.f;
            {
                uint32_t b0, b1, b2, b3, c0, c1, c2, c3;
                LDSM4T(b0, b1, b2, b3, bUH + p * 32);
                LDSM4T(c0, c1, c2, c3, bUL + p * 32);
                mma_bf16(u[0], xh0, xh1, xh2, xh3, b0, b1);
                mma_bf16(u[0], xl0, xl1, xl2, xl3, b0, b1);
                mma_bf16(u[0], xh0, xh1, xh2, xh3, c0, c1);
                mma_bf16(u[1], xh0, xh1, xh2, xh3, b2, b3);
                mma_bf16(u[1], xl0, xl1, xl2, xl3, b2, b3);
                mma_bf16(u[1], xh0, xh1, xh2, xh3, c2, c3);
            }
            {
                uint32_t b0, b1, b2, b3, c0, c1, c2, c3;
                LDSM4T(b0, b1, b2, b3, bRH + p * 32);
                LDSM4T(c0, c1, c2, c3, bRL + p * 32);
                mma_bf16(rr[0], rh0, rh1, rh2, rh3, b0, b1);
                mma_bf16(rr[0], rl0, rl1, rl2, rl3, b0, b1);
                mma_bf16(rr[0], rh0, rh1, rh2, rh3, c0, c1);
                mma_bf16(rr[1], rh0, rh1, rh2, rh3, b2, b3);
                mma_bf16(rr[1], rl0, rl1, rl2, rl3, b2, b3);
                mma_bf16(rr[1], rh0, rh1, rh2, rh3, c2, c3);
            }
            #pragma unroll
            for (int tt = 0; tt < 2; tt++) {
                int col = ch * 64 + (2 * p + tt) * 8 + cc;
                #pragma unroll
                for (int hh = 0; hh < 2; hh++) {
                    int row = rb * 16 + r_ + 8 * hh;
                    int a = sIdx[row];
                    if (a < 0) continue;
                    float2 mm = *(const float2*)(m + (size_t)(e0 + row) * 128 + col);
                    float h0 = (mm.x + ssilu(u[tt][2 * hh])) * rr[tt][2 * hh];
                    float h1 = (mm.y + ssilu(u[tt][2 * hh + 1])) * rr[tt][2 * hh + 1];
                    asm volatile("red.global.add.v2.f32 [%0], {%1,%2};"
                                 :: "l"(g_h + (size_t)a * 128 + col),
                                    "f"(h0), "f"(h1) : "memory");
                }
            }
        }
    }
}

// ---------------- K4: atom output GEMM ----------------
__global__ __launch_bounds__(256, 2) void k_atom_out(
    const float* __restrict__ Watom, float* __restrict__ out, int N)
{
    extern __shared__ float sm_[];
    float* sW = sm_;             // 16384 [k][j]
    float* sH = sm_ + 16384;     // 32*132

    int tid = threadIdx.x;
    for (int i = tid; i < 16384; i += 256) sW[i] = Watom[i];

    int ntiles = (N + 31) >> 5;
    int jt = tid & 31, et = tid >> 5;

    for (int tile = blockIdx.x; tile < ntiles; tile += gridDim.x) {
        int r0 = tile << 5;
        __syncthreads();
        for (int r = tid; r < 1024; r += 256) {
            int e = r >> 5, c = r & 31;
            float4 v = make_float4(0.f, 0.f, 0.f, 0.f);
            if (r0 + e < N) v = ((const float4*)(g_h + (size_t)(r0 + e) * 128))[c];
            *((float4*)&sH[e * 132 + c * 4]) = v;
        }
        __syncthreads();

        float acc[4][4];
        #pragma unroll
        for (int i = 0; i < 4; i++) {
            acc[i][0] = 0.f; acc[i][1] = 0.f; acc[i][2] = 0.f; acc[i][3] = 0.f;
        }
        #pragma unroll 4
        for (int k4 = 0; k4 < 32; k4++) {
            float4 mv[4];
            #pragma unroll
            for (int i = 0; i < 4; i++)
                mv[i] = *((float4*)&sH[(et * 4 + i) * 132 + k4 * 4]);
            #pragma unroll
            for (int kk = 0; kk < 4; kk++) {
                float4 w = *((float4*)&sW[(k4 * 4 + kk) * 128 + jt * 4]);
                #pragma unroll
                for (int i = 0; i < 4; i++) {
                    float mk = (kk == 0) ? mv[i].x : (kk == 1) ? mv[i].y
                             : (kk == 2) ? mv[i].z : mv[i].w;
                    acc[i][0] += mk * w.x;
                    acc[i][1] += mk * w.y;
                    acc[i][2] += mk * w.z;
                    acc[i][3] += mk * w.w;
                }
            }
        }
        #pragma unroll
        for (int i = 0; i < 4; i++) {
            int rrow = r0 + et * 4 + i;
            if (rrow < N) {
                float4 v;
                v.x = ssilu(acc[i][0]);
                v.y = ssilu(acc[i][1]);
                v.z = ssilu(acc[i][2]);
                v.w = ssilu(acc[i][3]);
                *((float4*)(out + (size_t)rrow * 128 + jt * 4)) = v;
            }
        }
        __syncthreads();
    }
}

extern "C" void kernel_launch(void* const* d_in, const int* in_sizes, int n_in,
                              void* d_out, int out_size) {
    const float* m     = (const float*)d_in[0];
    const float* rbf   = (const float*)d_in[1];
    const float* cbf   = (const float*)d_in[2];
    const int*   id3ba = (const int*)d_in[3];
    const int*   id3ca = (const int*)d_in[4];
    const int*   idxt  = (const int*)d_in[5];
    const float* Wba   = (const float*)d_in[6];
    const float* Wrbf  = (const float*)d_in[7];
    const float* Wdown = (const float*)d_in[8];
    const float* Wcbf  = (const float*)d_in[9];
    const float* Wup   = (const float*)d_in[10];
    const float* Wra   = (const float*)d_in[11];
    const float* Watom = (const float*)d_in[12];

    int E = in_sizes[0] / 128;
    int T = in_sizes[2] / 16;
    int N = out_size / 128;

    const int k4_smem = (16384 + 32 * 132) * 4;
    cudaFuncSetAttribute(k_edge_down_hmma,
                         cudaFuncAttributeMaxDynamicSharedMemorySize, K1_SMEM);
    cudaFuncSetAttribute(k_atom_out,
                         cudaFuncAttributeMaxDynamicSharedMemorySize, k4_smem);

    k_zero<<<512, 256>>>((E * 16) / 4, (N * 128) / 4);
    k_edge_down_hmma<<<148, 256, K1_SMEM>>>(m, rbf, Wba, Wrbf, Wdown, E);
    k_triplet<<<(T + 255) / 256, 256>>>(cbf, id3ba, id3ca, Wcbf, T);
    k_edge_up_hmma<<<1184, 256>>>(m, rbf, idxt, Wup, Wra, E);
    k_atom_out<<<(N + 31) / 32, 256, k4_smem>>>(Watom, (float*)d_out, N);
}

// round 9
// speedup vs baseline: 1.8702x; 1.0467x over previous
#include <cuda_runtime.h>
#include <cstdint>

#define SSCALE 1.6666666666666667f

__device__ __forceinline__ float ssilu(float x) {
    float e = __expf(-x);
    return SSCALE * __fdividef(x, 1.0f + e);
}

// ---- packed f32x2 helpers ----
__device__ __forceinline__ unsigned long long dup2(float x) {
    unsigned long long r;
    asm("mov.b64 %0, {%1, %1};" : "=l"(r) : "f"(x));
    return r;
}
__device__ __forceinline__ void up2(float& x, float& y, unsigned long long v) {
    asm("mov.b64 {%0, %1}, %2;" : "=f"(x), "=f"(y) : "l"(v));
}
#define FMA2(d, a, b) asm("fma.rn.f32x2 %0, %1, %2, %0;" : "+l"(d) : "l"(a), "l"(b))
#define MUL2(d, a, b) asm("mul.rn.f32x2 %0, %1, %2;" : "=l"(d) : "l"(a), "l"(b))

// ---- bf16 split + mma helpers ----
__device__ __forceinline__ void split2(float v0, float v1, uint32_t& hi, uint32_t& lo) {
    asm("cvt.rn.bf16x2.f32 %0, %1, %2;" : "=r"(hi) : "f"(v1), "f"(v0));
    float h0 = __uint_as_float(hi << 16);
    float h1 = __uint_as_float(hi & 0xFFFF0000u);
    float r0 = v0 - h0, r1 = v1 - h1;
    asm("cvt.rn.bf16x2.f32 %0, %1, %2;" : "=r"(lo) : "f"(r1), "f"(r0));
}
__device__ __forceinline__ void mma_bf16(float* d, uint32_t a0, uint32_t a1,
                                         uint32_t a2, uint32_t a3,
                                         uint32_t b0, uint32_t b1) {
    asm("mma.sync.aligned.m16n8k16.row.col.f32.bf16.bf16.f32 "
        "{%0,%1,%2,%3}, {%4,%5,%6,%7}, {%8,%9}, {%0,%1,%2,%3};"
        : "+f"(d[0]), "+f"(d[1]), "+f"(d[2]), "+f"(d[3])
        : "r"(a0), "r"(a1), "r"(a2), "r"(a3), "r"(b0), "r"(b1));
}
#define LDSM4(d0, d1, d2, d3, a) asm volatile( \
    "ldmatrix.sync.aligned.m8n8.x4.shared.b16 {%0,%1,%2,%3}, [%4];" \
    : "=r"(d0), "=r"(d1), "=r"(d2), "=r"(d3) : "r"(a))
#define LDSM4T(d0, d1, d2, d3, a) asm volatile( \
    "ldmatrix.sync.aligned.m8n8.x4.trans.shared.b16 {%0,%1,%2,%3}, [%4];" \
    : "=r"(d0), "=r"(d1), "=r"(d2), "=r"(d3) : "r"(a))

__device__ __forceinline__ uint32_t smem_u32(const void* p) {
    uint32_t a;
    asm("{ .reg .u64 t; cvta.to.shared.u64 t, %1; cvt.u32.u64 %0, t; }"
        : "=r"(a) : "l"(p));
    return a;
}

#define E_MAX 700000
#define N_MAX 40000

__device__ __align__(16) float g_xdown[(size_t)E_MAX * 16];
__device__ __align__(16) float g_xe[(size_t)E_MAX * 16];
__device__ __align__(16) float g_h[(size_t)N_MAX * 128];

// ---------------- K0: zero scratch ----------------
__global__ void k_zero(int n_xe4, int n_h4) {
    int i = blockIdx.x * blockDim.x + threadIdx.x;
    int stride = gridDim.x * blockDim.x;
    float4 z = make_float4(0.f, 0.f, 0.f, 0.f);
    for (int r = i; r < n_xe4; r += stride) ((float4*)g_xe)[r] = z;
    for (int r = i; r < n_h4; r += stride) ((float4*)g_h)[r] = z;
}

// ---------------- K1: edge dense + down projection (all HMMA) -------------
#define OFF_BH  0
#define OFF_BL  34816
#define OFF_WRH 69632
#define OFF_WRL 73984
#define OFF_WDH 78336
#define OFF_WDL 82432
#define OFF_AH  86528
#define OFF_AL  103936
#define OFF_RBH 121344
#define OFF_RBL 124416
#define K1_SMEM 127488

__global__ __launch_bounds__(256, 1) void k_edge_down_hmma(
    const float* __restrict__ m, const float* __restrict__ rbf,
    const float* __restrict__ Wba, const float* __restrict__ Wrbf,
    const float* __restrict__ Wdown, int E)
{
    extern __shared__ char smem[];
    uint32_t sb = smem_u32(smem);
    int tid = threadIdx.x;
    int l = tid & 31, w = tid >> 5;

    for (int i = tid; i < 8192; i += 256) {
        int k = i >> 6, n = (i & 63) * 2;
        float v0 = Wba[(size_t)k * 128 + n];
        float v1 = Wba[(size_t)k * 128 + n + 1];
        uint32_t hp, lp;
        split2(v0, v1, hp, lp);
        *(uint32_t*)(smem + OFF_BH + k * 272 + n * 2) = hp;
        *(uint32_t*)(smem + OFF_BL + k * 272 + n * 2) = lp;
    }
    for (int i = tid; i < 1024; i += 256) {
        int k = i >> 6, n = (i & 63) * 2;
        float v0 = Wrbf[(size_t)k * 128 + n];
        float v1 = Wrbf[(size_t)k * 128 + n + 1];
        uint32_t hp, lp;
        split2(v0, v1, hp, lp);
        *(uint32_t*)(smem + OFF_WRH + k * 272 + n * 2) = hp;
        *(uint32_t*)(smem + OFF_WRL + k * 272 + n * 2) = lp;
    }
    for (int i = tid; i < 1024; i += 256) {
        int k = i >> 3, n = (i & 7) * 2;
        float v0 = Wdown[(size_t)k * 16 + n];
        float v1 = Wdown[(size_t)k * 16 + n + 1];
        uint32_t hp, lp;
        split2(v0, v1, hp, lp);
        *(uint32_t*)(smem + OFF_WDH + k * 32 + n * 2) = hp;
        *(uint32_t*)(smem + OFF_WDL + k * 32 + n * 2) = lp;
    }

    int rowm = (l < 16) ? l : (l - 16);
    int colo = (l < 16) ? 0 : 8;
    int rb = w & 3, ch = w >> 2;
    int r_ = l >> 2, cc2 = (l & 3) * 2;

    uint32_t aH = sb + OFF_AH + (rb * 16 + rowm) * 272 + colo * 2;
    uint32_t aL = aH + (OFF_AL - OFF_AH);
    uint32_t rH = sb + OFF_RBH + (rb * 16 + rowm) * 48 + colo * 2;
    uint32_t rL = rH + (OFF_RBL - OFF_RBH);
    uint32_t bH = sb + OFF_BH + rowm * 272 + (ch * 64 + colo) * 2;
    uint32_t bL = bH + (OFF_BL - OFF_BH);
    uint32_t wrH = sb + OFF_WRH + rowm * 272 + (ch * 64 + colo) * 2;
    uint32_t wrL = wrH + (OFF_WRL - OFF_WRH);
    uint32_t wdH = sb + OFF_WDH + rowm * 32 + colo * 2;
    uint32_t wdL = wdH + (OFF_WDL - OFF_WDH);

    char* sXH = smem + OFF_AH;
    char* sXL = smem + OFF_AL;

    int ntiles = (E + 63) >> 6;
    for (int tile = blockIdx.x; tile < ntiles; tile += gridDim.x) {
        int e0 = tile << 6;
        __syncthreads();

        #pragma unroll 4
        for (int it = 0; it < 8; it++) {
            int r = tid + it * 256;
            int e = r >> 5, kq = r & 31;
            float4 v = make_float4(0.f, 0.f, 0.f, 0.f);
            if (e0 + e < E) v = *(const float4*)(m + (size_t)(e0 + e) * 128 + kq * 4);
            uint32_t h01, l01, h23, l23;
            split2(v.x, v.y, h01, l01);
            split2(v.z, v.w, h23, l23);
            *(unsigned long long*)(smem + OFF_AH + e * 272 + kq * 8) =
                ((unsigned long long)h23 << 32) | h01;
            *(unsigned long long*)(smem + OFF_AL + e * 272 + kq * 8) =
                ((unsigned long long)l23 << 32) | l01;
        }
        {
            int e = tid >> 2, kp = tid & 3;
            #pragma unroll
            for (int half = 0; half < 2; half++) {
                int k = (kp + half * 4) * 2;
                float2 v = make_float2(0.f, 0.f);
                if (e0 + e < E) v = *(const float2*)(rbf + (size_t)(e0 + e) * 16 + k);
                uint32_t hp, lp;
                split2(v.x, v.y, hp, lp);
                *(uint32_t*)(smem + OFF_RBH + e * 48 + k * 2) = hp;
                *(uint32_t*)(smem + OFF_RBL + e * 48 + k * 2) = lp;
            }
        }
        __syncthreads();

        float rw[8][4];
        #pragma unroll
        for (int t = 0; t < 8; t++) {
            rw[t][0] = 0.f; rw[t][1] = 0.f; rw[t][2] = 0.f; rw[t][3] = 0.f;
        }
        {
            uint32_t ra0, ra1, ra2, ra3, rl0, rl1, rl2, rl3;
            LDSM4(ra0, ra1, ra2, ra3, rH);
            LDSM4(rl0, rl1, rl2, rl3, rL);
            #pragma unroll
            for (int p = 0; p < 4; p++) {
                uint32_t b0, b1, b2, b3, c0, c1, c2, c3;
                LDSM4T(b0, b1, b2, b3, wrH + p * 32);
                LDSM4T(c0, c1, c2, c3, wrL + p * 32);
                mma_bf16(rw[p * 2], ra0, ra1, ra2, ra3, b0, b1);
                mma_bf16(rw[p * 2], rl0, rl1, rl2, rl3, b0, b1);
                mma_bf16(rw[p * 2], ra0, ra1, ra2, ra3, c0, c1);
                mma_bf16(rw[p * 2 + 1], ra0, ra1, ra2, ra3, b2, b3);
                mma_bf16(rw[p * 2 + 1], rl0, rl1, rl2, rl3, b2, b3);
                mma_bf16(rw[p * 2 + 1], ra0, ra1, ra2, ra3, c2, c3);
            }
        }

        float acc[8][4];
        #pragma unroll
        for (int t = 0; t < 8; t++) {
            acc[t][0] = 0.f; acc[t][1] = 0.f; acc[t][2] = 0.f; acc[t][3] = 0.f;
        }
        #pragma unroll
        for (int ks = 0; ks < 8; ks++) {
            uint32_t ah0, ah1, ah2, ah3, al0, al1, al2, al3;
            LDSM4(ah0, ah1, ah2, ah3, aH + ks * 32);
            LDSM4(al0, al1, al2, al3, aL + ks * 32);
            uint32_t bkb = bH + ks * 16 * 272;
            uint32_t lkb = bL + ks * 16 * 272;
            #pragma unroll
            for (int p = 0; p < 4; p++) {
                uint32_t b0, b1, b2, b3, c0, c1, c2, c3;
                LDSM4T(b0, b1, b2, b3, bkb + p * 32);
                LDSM4T(c0, c1, c2, c3, lkb + p * 32);
                mma_bf16(acc[p * 2], ah0, ah1, ah2, ah3, b0, b1);
                mma_bf16(acc[p * 2], al0, al1, al2, al3, b0, b1);
                mma_bf16(acc[p * 2], ah0, ah1, ah2, ah3, c0, c1);
                mma_bf16(acc[p * 2 + 1], ah0, ah1, ah2, ah3, b2, b3);
                mma_bf16(acc[p * 2 + 1], al0, al1, al2, al3, b2, b3);
                mma_bf16(acc[p * 2 + 1], ah0, ah1, ah2, ah3, c2, c3);
            }
        }

        __syncthreads();

        {
            int row0 = rb * 16 + r_;
            #pragma unroll
            for (int t = 0; t < 8; t++) {
                int colb = (ch * 64 + t * 8 + cc2) * 2;
                float x0 = ssilu(acc[t][0]) * rw[t][0];
                float x1 = ssilu(acc[t][1]) * rw[t][1];
                float x2 = ssilu(acc[t][2]) * rw[t][2];
                float x3 = ssilu(acc[t][3]) * rw[t][3];
                uint32_t hp, lp;
                split2(x0, x1, hp, lp);
                *(uint32_t*)(sXH + row0 * 272 + colb) = hp;
                *(uint32_t*)(sXL + row0 * 272 + colb) = lp;
                split2(x2, x3, hp, lp);
                *(uint32_t*)(sXH + (row0 + 8) * 272 + colb) = hp;
                *(uint32_t*)(sXL + (row0 + 8) * 272 + colb) = lp;
            }
        }
        __syncthreads();

        if (w < 4) {
            float d0[4] = {0.f, 0.f, 0.f, 0.f}, d1[4] = {0.f, 0.f, 0.f, 0.f};
            #pragma unroll
            for (int ks = 0; ks < 8; ks++) {
                uint32_t xh0, xh1, xh2, xh3, xl0, xl1, xl2, xl3;
                LDSM4(xh0, xh1, xh2, xh3, aH + ks * 32);
                LDSM4(xl0, xl1, xl2, xl3, aL + ks * 32);
                uint32_t b0, b1, b2, b3, c0, c1, c2, c3;
                LDSM4T(b0, b1, b2, b3, wdH + ks * 512);
                LDSM4T(c0, c1, c2, c3, wdL + ks * 512);
                mma_bf16(d0, xh0, xh1, xh2, xh3, b0, b1);
                mma_bf16(d0, xl0, xl1, xl2, xl3, b0, b1);
                mma_bf16(d0, xh0, xh1, xh2, xh3, c0, c1);
                mma_bf16(d1, xh0, xh1, xh2, xh3, b2, b3);
                mma_bf16(d1, xl0, xl1, xl2, xl3, b2, b3);
                mma_bf16(d1, xh0, xh1, xh2, xh3, c2, c3);
            }
            int e_row = e0 + rb * 16 + r_;
            if (e_row < E) {
                *(float2*)(g_xdown + (size_t)e_row * 16 + cc2) = make_float2(d0[0], d0[1]);
                *(float2*)(g_xdown + (size_t)e_row * 16 + 8 + cc2) = make_float2(d1[0], d1[1]);
            }
            if (e_row + 8 < E) {
                *(float2*)(g_xdown + (size_t)(e_row + 8) * 16 + cc2) = make_float2(d0[2], d0[3]);
                *(float2*)(g_xdown + (size_t)(e_row + 8) * 16 + 8 + cc2) = make_float2(d1[2], d1[3]);
            }
        }
    }
}

// ---------------- K2: triplet stage via HMMA ------------------------------
// x_t = x_down[ba] * (cbf @ W_cbf); g_xe[ca] += x_t (atomic)
// 128 triplets per block; cbf@Wcbf on mma.sync (3-pass split-bf16).
#define T3_CBH 0
#define T3_CBL 4096
#define T3_WCH 8192
#define T3_WCL 8704
#define T3_XD  9216
#define T3_BA  17408
#define T3_CA  17920
#define T3_SMEM 18432

__global__ __launch_bounds__(256) void k_triplet_hmma(
    const float* __restrict__ cbf,
    const int* __restrict__ ba, const int* __restrict__ ca,
    const float* __restrict__ Wcbf, int T)
{
    __shared__ __align__(16) char smem[T3_SMEM];
    uint32_t sb = smem_u32(smem);
    int tid = threadIdx.x;
    int l = tid & 31, w = tid >> 5;
    int t0 = blockIdx.x << 7;

    int* sBa = (int*)(smem + T3_BA);
    int* sCa = (int*)(smem + T3_CA);
    float* sXd = (float*)(smem + T3_XD);

    // W_cbf [16 s][16 d] -> hi/lo bf16, stride 32 B
    if (tid < 128) {
        int k = tid >> 3, n = (tid & 7) * 2;
        float v0 = Wcbf[k * 16 + n], v1 = Wcbf[k * 16 + n + 1];
        uint32_t hp, lp;
        split2(v0, v1, hp, lp);
        *(uint32_t*)(smem + T3_WCH + k * 32 + n * 2) = hp;
        *(uint32_t*)(smem + T3_WCL + k * 32 + n * 2) = lp;
    }
    // indices
    if (tid < 128) {
        int t = t0 + tid;
        bool ok = t < T;
        sBa[tid] = ok ? ba[t] : 0;
        sCa[tid] = ok ? ca[t] : -1;
    }
    // cbf tile [128][16] -> hi/lo bf16, stride 32 B
    {
        int e = tid >> 1, q = tid & 1;
        int t = t0 + e;
        bool ok = t < T;
        #pragma unroll
        for (int j = 0; j < 2; j++) {
            int qq = q * 2 + j;
            float4 v = make_float4(0.f, 0.f, 0.f, 0.f);
            if (ok) v = *(const float4*)(cbf + (size_t)t * 16 + qq * 4);
            uint32_t h01, l01, h23, l23;
            split2(v.x, v.y, h01, l01);
            split2(v.z, v.w, h23, l23);
            *(unsigned long long*)(smem + T3_CBH + e * 32 + qq * 8) =
                ((unsigned long long)h23 << 32) | h01;
            *(unsigned long long*)(smem + T3_CBL + e * 32 + qq * 8) =
                ((unsigned long long)l23 << 32) | l01;
        }
    }
    __syncthreads();

    // gather x_down[ba] -> sXd [128][16]
    {
        int r = tid >> 1, half = tid & 1;
        int b = sBa[r];
        float4 v0 = *(const float4*)(g_xdown + (size_t)b * 16 + half * 8);
        float4 v1 = *(const float4*)(g_xdown + (size_t)b * 16 + half * 8 + 4);
        *(float4*)&sXd[r * 16 + half * 8] = v0;
        *(float4*)&sXd[r * 16 + half * 8 + 4] = v1;
    }
    __syncthreads();

    // MMA: warp w handles rows w*16..w*16+15
    int rowm = (l < 16) ? l : (l - 16);
    int colo = (l < 16) ? 0 : 8;
    int r_ = l >> 2, cc = (l & 3) * 2;

    uint32_t aH = sb + T3_CBH + (w * 16 + rowm) * 32 + colo * 2;
    uint32_t aL = aH + (T3_CBL - T3_CBH);
    uint32_t bHa = sb + T3_WCH + rowm * 32 + colo * 2;
    uint32_t bLa = bHa + (T3_WCL - T3_WCH);

    uint32_t ah0, ah1, ah2, ah3, al0, al1, al2, al3;
    uint32_t b0, b1, b2, b3, c0, c1, c2, c3;
    LDSM4(ah0, ah1, ah2, ah3, aH);
    LDSM4(al0, al1, al2, al3, aL);
    LDSM4T(b0, b1, b2, b3, bHa);
    LDSM4T(c0, c1, c2, c3, bLa);

    float u[2][4];
    u[0][0]=u[0][1]=u[0][2]=u[0][3]=0.f;
    u[1][0]=u[1][1]=u[1][2]=u[1][3]=0.f;
    mma_bf16(u[0], ah0, ah1, ah2, ah3, b0, b1);
    mma_bf16(u[0], al0, al1, al2, al3, b0, b1);
    mma_bf16(u[0], ah0, ah1, ah2, ah3, c0, c1);
    mma_bf16(u[1], ah0, ah1, ah2, ah3, b2, b3);
    mma_bf16(u[1], al0, al1, al2, al3, b2, b3);
    mma_bf16(u[1], ah0, ah1, ah2, ah3, c2, c3);

    // epilogue: x_t = u * xdown, atomic scatter
    #pragma unroll
    for (int t = 0; t < 2; t++) {
        int col = t * 8 + cc;
        #pragma unroll
        for (int hh = 0; hh < 2; hh++) {
            int row = w * 16 + r_ + 8 * hh;
            int c = sCa[row];
            if (c < 0) continue;
            float2 xd = *(float2*)&sXd[row * 16 + col];
            float v0 = u[t][2 * hh] * xd.x;
            float v1 = u[t][2 * hh + 1] * xd.y;
            asm volatile("red.global.add.v2.f32 [%0], {%1,%2};"
                         :: "l"(g_xe + (size_t)c * 16 + col),
                            "f"(v0), "f"(v1) : "memory");
        }
    }
}

// ---------------- K3: edge up-projection + atom scatter (HMMA) ------------
#define OFF2_UPH 0
#define OFF2_UPL 4352
#define OFF2_RAH 8704
#define OFF2_RAL 13056
#define OFF2_XEH 17408
#define OFF2_XEL 20480
#define OFF2_RBH 23552
#define OFF2_RBL 26624
#define OFF2_IDX 29696
#define K3_SMEM  29952

__global__ __launch_bounds__(256, 2) void k_edge_up_hmma(
    const float* __restrict__ m, const float* __restrict__ rbf,
    const int* __restrict__ idxt,
    const float* __restrict__ Wup, const float* __restrict__ Wra, int E)
{
    __shared__ __align__(16) char smem[K3_SMEM];
    uint32_t sb = smem_u32(smem);
    int tid = threadIdx.x;
    int l = tid & 31, w = tid >> 5;

    for (int i = tid; i < 1024; i += 256) {
        int k = i >> 6, n = (i & 63) * 2;
        float v0 = Wup[(size_t)k * 128 + n], v1 = Wup[(size_t)k * 128 + n + 1];
        uint32_t hp, lp;
        split2(v0, v1, hp, lp);
        *(uint32_t*)(smem + OFF2_UPH + k * 272 + n * 2) = hp;
        *(uint32_t*)(smem + OFF2_UPL + k * 272 + n * 2) = lp;
        v0 = Wra[(size_t)k * 128 + n]; v1 = Wra[(size_t)k * 128 + n + 1];
        split2(v0, v1, hp, lp);
        *(uint32_t*)(smem + OFF2_RAH + k * 272 + n * 2) = hp;
        *(uint32_t*)(smem + OFF2_RAL + k * 272 + n * 2) = lp;
    }

    int rowm = (l < 16) ? l : (l - 16);
    int colo = (l < 16) ? 0 : 8;
    int rb = w & 3, ch = w >> 2;
    int r_ = l >> 2, cc = (l & 3) * 2;

    uint32_t xH = sb + OFF2_XEH + (rb * 16 + rowm) * 48 + colo * 2;
    uint32_t xL = xH + (OFF2_XEL - OFF2_XEH);
    uint32_t rbH = sb + OFF2_RBH + (rb * 16 + rowm) * 48 + colo * 2;
    uint32_t rbL = rbH + (OFF2_RBL - OFF2_RBH);
    uint32_t bUH = sb + OFF2_UPH + rowm * 272 + (ch * 64 + colo) * 2;
    uint32_t bUL = bUH + (OFF2_UPL - OFF2_UPH);
    uint32_t bRH = sb + OFF2_RAH + rowm * 272 + (ch * 64 + colo) * 2;
    uint32_t bRL = bRH + (OFF2_RAL - OFF2_RAH);
    int* sIdx = (int*)(smem + OFF2_IDX);

    int ntiles = (E + 63) >> 6;
    for (int tile = blockIdx.x; tile < ntiles; tile += gridDim.x) {
        int e0 = tile << 6;
        __syncthreads();

        {
            int e = tid >> 2, q = tid & 3;
            float4 vx = make_float4(0.f, 0.f, 0.f, 0.f), vr = vx;
            if (e0 + e < E) {
                vx = *(const float4*)(g_xe + (size_t)(e0 + e) * 16 + q * 4);
                vr = *(const float4*)(rbf + (size_t)(e0 + e) * 16 + q * 4);
            }
            uint32_t h01, l01, h23, l23;
            split2(vx.x, vx.y, h01, l01); split2(vx.z, vx.w, h23, l23);
            *(unsigned long long*)(smem + OFF2_XEH + e * 48 + q * 8) =
                ((unsigned long long)h23 << 32) | h01;
            *(unsigned long long*)(smem + OFF2_XEL + e * 48 + q * 8) =
                ((unsigned long long)l23 << 32) | l01;
            split2(vr.x, vr.y, h01, l01); split2(vr.z, vr.w, h23, l23);
            *(unsigned long long*)(smem + OFF2_RBH + e * 48 + q * 8) =
                ((unsigned long long)h23 << 32) | h01;
            *(unsigned long long*)(smem + OFF2_RBL + e * 48 + q * 8) =
                ((unsigned long long)l23 << 32) | l01;
        }
        if (tid < 64) sIdx[tid] = (e0 + tid < E) ? idxt[e0 + tid] : -1;
        __syncthreads();

        uint32_t xh0, xh1, xh2, xh3, xl0, xl1, xl2, xl3;
        uint32_t rh0, rh1, rh2, rh3, rl0, rl1, rl2, rl3;
        LDSM4(xh0, xh1, xh2, xh3, xH);
        LDSM4(xl0, xl1, xl2, xl3, xL);
        LDSM4(rh0, rh1, rh2, rh3, rbH);
        LDSM4(rl0, rl1, rl2, rl3, rbL);

        #pragma unroll
        for (int p = 0; p < 4; p++) {
            float u[2][4], rr[2][4];
            u[0][0]=u[0][1]=u[0][2]=u[0][3]=0.f;
            u[1][0]=u[1][1]=u[1][2]=u[1][3]=0.f;
            rr[0][0]=rr[0][1]=rr[0][2]=rr[0][3]=0.f;
            rr[1][0]=rr[1][1]=rr[1][2]=rr[1][3]=0.f;
            {
                uint32_t b0, b1, b2, b3, c0, c1, c2, c3;
                LDSM4T(b0, b1, b2, b3, bUH + p * 32);
                LDSM4T(c0, c1, c2, c3, bUL + p * 32);
                mma_bf16(u[0], xh0, xh1, xh2, xh3, b0, b1);
                mma_bf16(u[0], xl0, xl1, xl2, xl3, b0, b1);
                mma_bf16(u[0], xh0, xh1, xh2, xh3, c0, c1);
                mma_bf16(u[1], xh0, xh1, xh2, xh3, b2, b3);
                mma_bf16(u[1], xl0, xl1, xl2, xl3, b2, b3);
                mma_bf16(u[1], xh0, xh1, xh2, xh3, c2, c3);
            }
            {
                uint32_t b0, b1, b2, b3, c0, c1, c2, c3;
                LDSM4T(b0, b1, b2, b3, bRH + p * 32);
                LDSM4T(c0, c1, c2, c3, bRL + p * 32);
                mma_bf16(rr[0], rh0, rh1, rh2, rh3, b0, b1);
                mma_bf16(rr[0], rl0, rl1, rl2, rl3, b0, b1);
                mma_bf16(rr[0], rh0, rh1, rh2, rh3, c0, c1);
                mma_bf16(rr[1], rh0, rh1, rh2, rh3, b2, b3);
                mma_bf16(rr[1], rl0, rl1, rl2, rl3, b2, b3);
                mma_bf16(rr[1], rh0, rh1, rh2, rh3, c2, c3);
            }
            #pragma unroll
            for (int tt = 0; tt < 2; tt++) {
                int col = ch * 64 + (2 * p + tt) * 8 + cc;
                #pragma unroll
                for (int hh = 0; hh < 2; hh++) {
                    int row = rb * 16 + r_ + 8 * hh;
                    int a = sIdx[row];
                    if (a < 0) continue;
                    float2 mm = *(const float2*)(m + (size_t)(e0 + row) * 128 + col);
                    float h0 = (mm.x + ssilu(u[tt][2 * hh])) * rr[tt][2 * hh];
                    float h1 = (mm.y + ssilu(u[tt][2 * hh + 1])) * rr[tt][2 * hh + 1];
                    asm volatile("red.global.add.v2.f32 [%0], {%1,%2};"
                                 :: "l"(g_h + (size_t)a * 128 + col),
                                    "f"(h0), "f"(h1) : "memory");
                }
            }
        }
    }
}

// ---------------- K4: atom output GEMM ----------------
__global__ __launch_bounds__(256, 2) void k_atom_out(
    const float* __restrict__ Watom, float* __restrict__ out, int N)
{
    extern __shared__ float sm_[];
    float* sW = sm_;
    float* sH = sm_ + 16384;

    int tid = threadIdx.x;
    for (int i = tid; i < 16384; i += 256) sW[i] = Watom[i];

    int ntiles = (N + 31) >> 5;
    int jt = tid & 31, et = tid >> 5;

    for (int tile = blockIdx.x; tile < ntiles; tile += gridDim.x) {
        int r0 = tile << 5;
        __syncthreads();
        for (int r = tid; r < 1024; r += 256) {
            int e = r >> 5, c = r & 31;
            float4 v = make_float4(0.f, 0.f, 0.f, 0.f);
            if (r0 + e < N) v = ((const float4*)(g_h + (size_t)(r0 + e) * 128))[c];
            *((float4*)&sH[e * 132 + c * 4]) = v;
        }
        __syncthreads();

        float acc[4][4];
        #pragma unroll
        for (int i = 0; i < 4; i++) {
            acc[i][0] = 0.f; acc[i][1] = 0.f; acc[i][2] = 0.f; acc[i][3] = 0.f;
        }
        #pragma unroll 4
        for (int k4 = 0; k4 < 32; k4++) {
            float4 mv[4];
            #pragma unroll
            for (int i = 0; i < 4; i++)
                mv[i] = *((float4*)&sH[(et * 4 + i) * 132 + k4 * 4]);
            #pragma unroll
            for (int kk = 0; kk < 4; kk++) {
                float4 w = *((float4*)&sW[(k4 * 4 + kk) * 128 + jt * 4]);
                #pragma unroll
                for (int i = 0; i < 4; i++) {
                    float mk = (kk == 0) ? mv[i].x : (kk == 1) ? mv[i].y
                             : (kk == 2) ? mv[i].z : mv[i].w;
                    acc[i][0] += mk * w.x;
                    acc[i][1] += mk * w.y;
                    acc[i][2] += mk * w.z;
                    acc[i][3] += mk * w.w;
                }
            }
        }
        #pragma unroll
        for (int i = 0; i < 4; i++) {
            int rrow = r0 + et * 4 + i;
            if (rrow < N) {
                float4 v;
                v.x = ssilu(acc[i][0]);
                v.y = ssilu(acc[i][1]);
                v.z = ssilu(acc[i][2]);
                v.w = ssilu(acc[i][3]);
                *((float4*)(out + (size_t)rrow * 128 + jt * 4)) = v;
            }
        }
        __syncthreads();
    }
}

extern "C" void kernel_launch(void* const* d_in, const int* in_sizes, int n_in,
                              void* d_out, int out_size) {
    const float* m     = (const float*)d_in[0];
    const float* rbf   = (const float*)d_in[1];
    const float* cbf   = (const float*)d_in[2];
    const int*   id3ba = (const int*)d_in[3];
    const int*   id3ca = (const int*)d_in[4];
    const int*   idxt  = (const int*)d_in[5];
    const float* Wba   = (const float*)d_in[6];
    const float* Wrbf  = (const float*)d_in[7];
    const float* Wdown = (const float*)d_in[8];
    const float* Wcbf  = (const float*)d_in[9];
    const float* Wup   = (const float*)d_in[10];
    const float* Wra   = (const float*)d_in[11];
    const float* Watom = (const float*)d_in[12];

    int E = in_sizes[0] / 128;
    int T = in_sizes[2] / 16;
    int N = out_size / 128;

    const int k4_smem = (16384 + 32 * 132) * 4;
    cudaFuncSetAttribute(k_edge_down_hmma,
                         cudaFuncAttributeMaxDynamicSharedMemorySize, K1_SMEM);
    cudaFuncSetAttribute(k_atom_out,
                         cudaFuncAttributeMaxDynamicSharedMemorySize, k4_smem);

    k_zero<<<512, 256>>>((E * 16) / 4, (N * 128) / 4);
    k_edge_down_hmma<<<148, 256, K1_SMEM>>>(m, rbf, Wba, Wrbf, Wdown, E);
    k_triplet_hmma<<<(T + 127) / 128, 256>>>(cbf, id3ba, id3ca, Wcbf, T);
    k_edge_up_hmma<<<1184, 256>>>(m, rbf, idxt, Wup, Wra, E);
    k_atom_out<<<(N + 31) / 32, 256, k4_smem>>>(Watom, (float*)d_out, N);
}